// round 7
// baseline (speedup 1.0000x reference)
#include <cuda_runtime.h>
#include <cuda_bf16.h>
#include <math.h>

#define IMG_H 512
#define IMG_W 640
#define HW (IMG_H * IMG_W)            // 327680
#define FXc 500.0f
#define FYc 500.0f
#define CXc 320.0f
#define CYc 256.0f

#define GRID 144                      // <= 148 SMs -> all blocks co-resident
#define TPB 1024
#define PPT 4                         // points per thread per iter in project

#define NSCAN_BLOCKS 320              // HW / 1024
#define NPAD 524288                   // 2^19 >= n_valid
#define NCHUNK 256                    // NPAD / 2048
#define KMAX 12

// ---------------- device scratch ----------------
__device__ unsigned int g_cntbuf[HW + 1];   // [HW] = nvalid append counter
__device__ unsigned int g_off[HW];
__device__ unsigned int g_woff[HW];
__device__ unsigned int g_bsum[NSCAN_BLOCKS];
__device__ unsigned int g_barCnt;           // zero-init; self-resetting
__device__ volatile unsigned int g_barGen;  // monotonic across replays

__device__ float4 g_rec[NPAD];   // unordered: {pid_bits, z, w, idx_bits}
__device__ float4 g_srec[NPAD];  // binned+sorted: {z, w, idx_bits, unused}
__device__ float g_x[NPAD];      // lg at sorted positions (zero-pad via guard)
__device__ float g_S[NPAD];      // inclusive scan, assoc-scan rounding replicated
__device__ float g_L11[NCHUNK];

// ---------------- software grid barrier (all blocks resident) -------------
__device__ __forceinline__ void grid_barrier()
{
    __syncthreads();
    if (threadIdx.x == 0) {
        unsigned int gen = g_barGen;
        __threadfence();
        if (atomicAdd(&g_barCnt, 1u) == GRID - 1) {
            g_barCnt = 0;            // reset BEFORE release -> replay-safe
            __threadfence();
            g_barGen = gen + 1;
        } else {
            while (g_barGen == gen) { __nanosleep(64); }
        }
        __threadfence();
    }
    __syncthreads();
}

__device__ __forceinline__ bool rec_before(const float4& a, const float4& b)
{
    if (a.x != b.x) return a.x > b.x;                   // z desc
    return __float_as_uint(a.z) < __float_as_uint(b.z); // idx asc
}

// ---------------- the whole pipeline in one kernel -------------------------
__global__ void __launch_bounds__(TPB, 1)
mega_kernel(const float4* __restrict__ means4,
            const float* __restrict__ means,
            const float* __restrict__ opac,
            const float* __restrict__ feats,
            const float* __restrict__ pose,
            float* __restrict__ out, int n)
{
    __shared__ float sF[7168];          // 28 KB scratch, aliased per phase
    __shared__ float sS11[256];
    __shared__ unsigned int wcnt[32];
    __shared__ unsigned int woffs[32];
    __shared__ unsigned int sbase_sh;
    unsigned int* sU = (unsigned int*)sF;

    const int t = threadIdx.x;
    const int bid = blockIdx.x;
    const int lane = t & 31;
    const int warp = t >> 5;

    // ===== phase 0: zero counters =====
    for (int i = bid * TPB + t; i < HW + 1; i += GRID * TPB)
        g_cntbuf[i] = 0;
    grid_barrier();

    // ===== phase 1: project (R1-verified rounding), count + append =====
    for (int base = bid * (TPB * PPT); base < n; base += GRID * TPB * PPT) {
        int i0 = base + t * PPT;
        float m[PPT][3];
        bool valid[PPT];
        int pid[PPT];
        float zv[PPT];
        unsigned int cnt = 0;

#pragma unroll
        for (int q = 0; q < PPT; q++) { m[q][0] = 0.0f; m[q][1] = 0.0f; m[q][2] = -1.0f; }
        if (i0 + PPT <= n) {
            int v = i0 >> 2;
            float4 a = means4[3 * v + 0];
            float4 b = means4[3 * v + 1];
            float4 c = means4[3 * v + 2];
            m[0][0] = a.x; m[0][1] = a.y; m[0][2] = a.z;
            m[1][0] = a.w; m[1][1] = b.x; m[1][2] = b.y;
            m[2][0] = b.z; m[2][1] = b.w; m[2][2] = c.x;
            m[3][0] = c.y; m[3][1] = c.z; m[3][2] = c.w;
        } else if (i0 < n) {
            for (int q = 0; q < PPT; q++)
                if (i0 + q < n) {
                    m[q][0] = means[3 * (i0 + q) + 0];
                    m[q][1] = means[3 * (i0 + q) + 1];
                    m[q][2] = means[3 * (i0 + q) + 2];
                }
        }

#pragma unroll
        for (int q = 0; q < PPT; q++) {
            float m0 = m[q][0], m1 = m[q][1], m2 = m[q][2];
            // pose is identity: exact regardless of order
            float pc0 = m0 * pose[0] + m1 * pose[1] + m2 * pose[2]  + pose[3];
            float pc1 = m0 * pose[4] + m1 * pose[5] + m2 * pose[6]  + pose[7];
            float z   = m0 * pose[8] + m1 * pose[9] + m2 * pose[10] + pose[11];
            // IEEE rn div/mul/add, NO fma (matches reference; measured)
            float x = __fadd_rn(__fmul_rn(__fdiv_rn(pc0, z), FXc), CXc);
            float y = __fadd_rn(__fmul_rn(__fdiv_rn(pc1, z), FYc), CYc);
            bool ok = (i0 + q < n) && (x >= 0.0f) && (x < (float)IMG_W) &&
                      (y >= 0.0f) && (y < (float)IMG_H) && (z > 0.0f);
            valid[q] = ok;
            if (ok) {
                pid[q] = (int)floorf(y) * IMG_W + (int)floorf(x);
                zv[q] = z;
                cnt++;
            }
        }

        unsigned int pre = cnt;
#pragma unroll
        for (int d = 1; d < 32; d <<= 1) {
            unsigned int u = __shfl_up_sync(0xffffffffu, pre, d);
            if (lane >= d) pre += u;
        }
        if (lane == 31) wcnt[warp] = pre;
        __syncthreads();
        if (t == 0) {
            unsigned int run = 0;
#pragma unroll
            for (int wi = 0; wi < 32; wi++) { woffs[wi] = run; run += wcnt[wi]; }
            sbase_sh = (run > 0) ? atomicAdd(&g_cntbuf[HW], run) : 0u;
        }
        __syncthreads();

        unsigned int pos = sbase_sh + woffs[warp] + (pre - cnt);
#pragma unroll
        for (int q = 0; q < PPT; q++) {
            if (valid[q]) {
                atomicAdd(&g_cntbuf[pid[q]], 1u);
                if (pos < NPAD)
                    g_rec[pos] = make_float4(__int_as_float(pid[q]), zv[q],
                                             opac[i0 + q],
                                             __int_as_float(i0 + q));
                pos++;
            }
        }
    }
    grid_barrier();

    unsigned int nvalid = g_cntbuf[HW];
    if (nvalid > NPAD) nvalid = NPAD;

    // ===== phase 2a: per-chunk count sums =====
    for (int c = bid; c < NSCAN_BLOCKS; c += GRID) {
        sU[t] = g_cntbuf[c * 1024 + t];
        __syncthreads();
        for (int d = 512; d > 0; d >>= 1) {
            if (t < d) sU[t] += sU[t + d];
            __syncthreads();
        }
        if (t == 0) g_bsum[c] = sU[0];
        __syncthreads();
    }
    grid_barrier();

    // ===== phase 2b: offsets (redundant top scan per block) =====
    {
        unsigned int* sTb = sU + 1024;
        if (t < 512) sTb[t] = (t < NSCAN_BLOCKS) ? g_bsum[t] : 0u;
        __syncthreads();
        for (int d = 1; d < 512; d <<= 1) {
            unsigned int add = (t < 512 && t >= d) ? sTb[t - d] : 0u;
            __syncthreads();
            if (t < 512) sTb[t] += add;
            __syncthreads();
        }
        for (int c = bid; c < NSCAN_BLOCKS; c += GRID) {
            int gi = c * 1024 + t;
            unsigned int v = g_cntbuf[gi];
            sU[t] = v;
            __syncthreads();
            for (int d = 1; d < 1024; d <<= 1) {
                unsigned int add = (t >= d) ? sU[t - d] : 0u;
                __syncthreads();
                sU[t] += add;
                __syncthreads();
            }
            unsigned int o = sU[t] - v + ((c > 0) ? sTb[c - 1] : 0u);
            g_off[gi] = o;
            g_woff[gi] = o;
            __syncthreads();
        }
    }
    grid_barrier();

    // ===== phase 3: place records into bins (pipelined) =====
    {
        unsigned int stride = GRID * TPB;
        unsigned int r = bid * TPB + t;
        bool have = (r < nvalid);
        float4 rec;
        if (have) rec = g_rec[r];
        while (have) {
            unsigned int rn = r + stride;
            bool haveN = (rn < nvalid);
            float4 recN;
            if (haveN) recN = g_rec[rn];          // prefetch past the atomic
            int pid = __float_as_int(rec.x);
            unsigned int pos = atomicAdd(&g_woff[pid], 1u);
            if (pos < NPAD)
                g_srec[pos] = make_float4(rec.y, rec.z, rec.w, 0.0f);
            r = rn; rec = recN; have = haveN;
        }
    }
    grid_barrier();

    // ===== phase 4: per-pixel sort (z desc, idx asc) + emit lg =====
    for (int p = bid * TPB + t; p < HW; p += GRID * TPB) {
        unsigned int s = g_off[p];
        unsigned int k = g_cntbuf[p];
        if (k == 0) continue;
        if (k <= KMAX) {
            float4 a[KMAX];
            for (unsigned int i = 0; i < k; i++) a[i] = g_srec[s + i];
            for (unsigned int i = 1; i < k; i++) {
                float4 key = a[i];
                int j = (int)i - 1;
                while (j >= 0 && rec_before(key, a[j])) { a[j + 1] = a[j]; j--; }
                a[j + 1] = key;
            }
            for (unsigned int i = 0; i < k; i++) {
                g_srec[s + i] = a[i];
                g_x[s + i] = log1pf(-a[i].y);
            }
        } else {
            for (unsigned int i = 0; i < k; i++) {
                unsigned int best = i;
                float4 bv = g_srec[s + i];
                for (unsigned int j = i + 1; j < k; j++) {
                    float4 cv = g_srec[s + j];
                    if (rec_before(cv, bv)) { best = j; bv = cv; }
                }
                if (best != i) {
                    float4 tmp = g_srec[s + i];
                    g_srec[s + i] = bv;
                    g_srec[s + best] = tmp;
                }
                g_x[s + i] = log1pf(-bv.y);
            }
        }
    }
    grid_barrier();

    // ===== phase 5: per-chunk pairwise tree sum (levels 1..11) =====
    for (int c = bid; c < NCHUNK; c += GRID) {
        int base = c * 2048;
        sF[t]        = ((unsigned int)(base + t) < nvalid) ? g_x[base + t] : 0.0f;
        sF[t + 1024] = ((unsigned int)(base + t + 1024) < nvalid) ? g_x[base + t + 1024] : 0.0f;
        __syncthreads();
        for (int size = 1024; size >= 1; size >>= 1) {
            float v = 0.0f;
            if (t < size) v = sF[2 * t] + sF[2 * t + 1];
            __syncthreads();
            if (t < size) sF[t] = v;
            __syncthreads();
        }
        if (t == 0) g_L11[c] = sF[0];
        __syncthreads();
    }
    grid_barrier();

    // ===== phase 6: mid scan (redundant per block) + up-sweep =====
    {
        float* Lv = sF;          // [0..510]
        float* Sv = sF + 512;    // [0..510]
        if (t < 256) Lv[t] = g_L11[t];
        __syncthreads();
        int off = 0, size = 256;
        for (int d = 0; d < 8; d++) {
            int noff = off + size, nsz = size >> 1;
            if (t < nsz) Lv[noff + t] = Lv[off + 2 * t] + Lv[off + 2 * t + 1];
            __syncthreads();
            off = noff; size = nsz;
        }
        if (t == 0) Sv[510] = Lv[510];
        __syncthreads();
        for (int d = 0; d < 8; d++) {
            int sz = 2 << d;
            off -= sz;
            int poff = off + sz;
            if (t < sz) {
                float v;
                if (t == 0)      v = Lv[off];
                else if (t & 1)  v = Sv[poff + ((t - 1) >> 1)];
                else             v = Sv[poff + (t >> 1) - 1] + Lv[off + t];
                Sv[off + t] = v;
            }
            __syncthreads();
        }
        if (t < 256) sS11[t] = Sv[t];
        __syncthreads();

        float* Lb = sF;          // [0..4093]
        float* Sa = sF + 4096;   // [0..2047]
        float* Sb = sF + 6144;   // [0..1023]
        for (int c = bid; c < NCHUNK; c += GRID) {
            int base = c * 2048;
            Lb[t]        = ((unsigned int)(base + t) < nvalid) ? g_x[base + t] : 0.0f;
            Lb[t + 1024] = ((unsigned int)(base + t + 1024) < nvalid) ? g_x[base + t + 1024] : 0.0f;
            __syncthreads();
            int off2 = 0, size2 = 2048;
            for (int d = 1; d <= 10; d++) {
                int noff = off2 + size2, nsz = size2 >> 1;
                for (int j = t; j < nsz; j += TPB)
                    Lb[noff + j] = Lb[off2 + 2 * j] + Lb[off2 + 2 * j + 1];
                __syncthreads();
                off2 = noff; size2 = nsz;
            }
            float bound = (c > 0) ? sS11[c - 1] : 0.0f;
            if (t == 0) {
                Sa[0] = (c == 0) ? Lb[off2] : bound + Lb[off2];
                Sa[1] = sS11[c];
            }
            __syncthreads();
            for (int d = 9; d >= 0; d--) {
                int sz = 2048 >> d;
                off2 -= sz;
                float* Sprev = (d & 1) ? Sa : Sb;
                float* Scur  = (d & 1) ? Sb : Sa;
                for (int j = t; j < sz; j += TPB) {
                    float v;
                    if (j == 0)      v = (c == 0) ? Lb[off2] : bound + Lb[off2];
                    else if (j & 1)  v = Sprev[(j - 1) >> 1];
                    else             v = Sprev[(j >> 1) - 1] + Lb[off2 + j];
                    Scur[j] = v;
                }
                __syncthreads();
            }
            g_S[base + t] = Sa[t];
            g_S[base + t + 1024] = Sa[t + 1024];
            __syncthreads();
        }
    }
    grid_barrier();

    // ===== phase 7: render =====
    for (int p = bid * TPB + t; p < HW; p += GRID * TPB) {
        unsigned int s = g_off[p];
        unsigned int k = g_cntbuf[p];

        float img0 = 0.0f, img1 = 0.0f, img2 = 0.0f;
        float dep = 0.0f;
        float Lsum = 0.0f;

        float c_end = (k > 0) ? g_S[s + k - 1] : 0.0f;
        for (unsigned int i = 0; i < k; i++) {
            float4 r = __ldcg(&g_srec[s + i]);   // bypass possibly-stale L1
            float T = expf(c_end - g_S[s + i]);
            float contrib = r.y * T;
            unsigned int idx = __float_as_uint(r.z);
            img0 += contrib * feats[3 * idx + 0];
            img1 += contrib * feats[3 * idx + 1];
            img2 += contrib * feats[3 * idx + 2];
            dep  += contrib * r.x;
            Lsum += g_x[s + i];
        }

        out[0 * HW + p] = img0;
        out[1 * HW + p] = img1;
        out[2 * HW + p] = img2;
        out[3 * HW + p] = dep;
        out[4 * HW + p] = 1.0f - expf(Lsum);
    }
}

// ---------------- launch: ONE graph node ----------------
extern "C" void kernel_launch(void* const* d_in, const int* in_sizes, int n_in,
                              void* d_out, int out_size)
{
    const float* means = (const float*)d_in[0];
    const float* opac  = (const float*)d_in[1];
    const float* feats = (const float*)d_in[2];
    const float* pose  = (const float*)d_in[3];
    float* out = (float*)d_out;

    int n = in_sizes[0] / 3;

    mega_kernel<<<GRID, TPB>>>((const float4*)means, means, opac, feats,
                               pose, out, n);
}

// round 8
// speedup vs baseline: 1.1254x; 1.1254x over previous
#include <cuda_runtime.h>
#include <cuda_bf16.h>
#include <math.h>

#define IMG_H 512
#define IMG_W 640
#define HW (IMG_H * IMG_W)            // 327680
#define FXc 500.0f
#define FYc 500.0f
#define CXc 320.0f
#define CYc 256.0f

#define NSCAN_BLOCKS 320              // HW / 1024
#define GRID_SC 128                   // co-resident scan grid (<148 SMs)
#define NPAD 524288                   // 2^19 >= n_valid (~345k)
#define NCHUNK 256                    // NPAD / 2048
#define KMAX 24

#define PRJ_TPB 256
#define PRJ_WARPS (PRJ_TPB / 32)
#define PPT 4                         // points per thread (project)
#define RPT 4                         // records per thread (place)

// ---------------- device scratch ----------------
__device__ unsigned int g_cntbuf[HW + 1];   // [HW] = nvalid append counter
__device__ unsigned int g_off[HW];
__device__ unsigned int g_woff[HW];
__device__ unsigned int g_bsum[NSCAN_BLOCKS];
__device__ unsigned int g_tick;             // scan_down last-block ticket
__device__ unsigned int g_barCnt;           // scan_fused barrier (self-reset)
__device__ volatile unsigned int g_barGen;

__device__ float4 g_rec[NPAD];   // unordered: {pid_bits, z, w, idx_bits}
__device__ float4 g_srec[NPAD];  // binned+sorted: {z, w, idx_bits, unused}
__device__ float g_x[NPAD];      // lg at sorted positions (zero-pad via guard)
__device__ float g_S[NPAD];      // inclusive scan, assoc-scan rounding replicated
__device__ float g_L11[NCHUNK];
__device__ float g_S11[NCHUNK];

// ---------------- pass 1: project 4 pts/thread (R1-verified rounding) -----
__global__ void project_count_kernel(const float4* __restrict__ means4,
                                     const float* __restrict__ means,
                                     const float* __restrict__ opac,
                                     const float* __restrict__ pose, int n)
{
    __shared__ unsigned int wcnt[PRJ_WARPS];
    __shared__ unsigned int woffs[PRJ_WARPS];
    __shared__ unsigned int sbase;

    int tbase = (blockIdx.x * blockDim.x + threadIdx.x) * PPT;
    int lane = threadIdx.x & 31;
    int warp = threadIdx.x >> 5;

    float m[PPT][3];
    bool valid[PPT];
    int pid[PPT];
    float zv[PPT];
    unsigned int cnt = 0;

#pragma unroll
    for (int q = 0; q < PPT; q++) { m[q][0] = 0.0f; m[q][1] = 0.0f; m[q][2] = -1.0f; }
    if (tbase + PPT <= n) {
        int v = tbase >> 2;
        float4 a = means4[3 * v + 0];
        float4 b = means4[3 * v + 1];
        float4 c = means4[3 * v + 2];
        m[0][0] = a.x; m[0][1] = a.y; m[0][2] = a.z;
        m[1][0] = a.w; m[1][1] = b.x; m[1][2] = b.y;
        m[2][0] = b.z; m[2][1] = b.w; m[2][2] = c.x;
        m[3][0] = c.y; m[3][1] = c.z; m[3][2] = c.w;
    } else if (tbase < n) {
        for (int q = 0; q < PPT; q++)
            if (tbase + q < n) {
                m[q][0] = means[3 * (tbase + q) + 0];
                m[q][1] = means[3 * (tbase + q) + 1];
                m[q][2] = means[3 * (tbase + q) + 2];
            }
    }

#pragma unroll
    for (int q = 0; q < PPT; q++) {
        float m0 = m[q][0], m1 = m[q][1], m2 = m[q][2];
        // pose is identity: exact regardless of order
        float pc0 = m0 * pose[0] + m1 * pose[1] + m2 * pose[2]  + pose[3];
        float pc1 = m0 * pose[4] + m1 * pose[5] + m2 * pose[6]  + pose[7];
        float z   = m0 * pose[8] + m1 * pose[9] + m2 * pose[10] + pose[11];
        // IEEE rn div/mul/add, NO fma (matches reference; measured best)
        float x = __fadd_rn(__fmul_rn(__fdiv_rn(pc0, z), FXc), CXc);
        float y = __fadd_rn(__fmul_rn(__fdiv_rn(pc1, z), FYc), CYc);
        bool ok = (tbase + q < n) && (x >= 0.0f) && (x < (float)IMG_W) &&
                  (y >= 0.0f) && (y < (float)IMG_H) && (z > 0.0f);
        valid[q] = ok;
        if (ok) {
            pid[q] = (int)floorf(y) * IMG_W + (int)floorf(x);
            zv[q] = z;
            cnt++;
        }
    }

    unsigned int pre = cnt;
#pragma unroll
    for (int d = 1; d < 32; d <<= 1) {
        unsigned int u = __shfl_up_sync(0xffffffffu, pre, d);
        if (lane >= d) pre += u;
    }
    if (lane == 31) wcnt[warp] = pre;
    __syncthreads();
    if (threadIdx.x == 0) {
        unsigned int run = 0;
#pragma unroll
        for (int wi = 0; wi < PRJ_WARPS; wi++) { woffs[wi] = run; run += wcnt[wi]; }
        sbase = (run > 0) ? atomicAdd(&g_cntbuf[HW], run) : 0u;
    }
    __syncthreads();

    unsigned int pos = sbase + woffs[warp] + (pre - cnt);
#pragma unroll
    for (int q = 0; q < PPT; q++) {
        if (valid[q]) {
            atomicAdd(&g_cntbuf[pid[q]], 1u);
            if (pos < NPAD)
                g_rec[pos] = make_float4(__int_as_float(pid[q]), zv[q],
                                         opac[tbase + q],
                                         __int_as_float(tbase + q));
            pos++;
        }
    }
}

// ---------------- fused offset scan (reduce + offsets, ticket barrier) ----
__device__ __forceinline__ void grid_barrier_sc()
{
    __syncthreads();
    if (threadIdx.x == 0) {
        unsigned int gen = g_barGen;
        __threadfence();
        if (atomicAdd(&g_barCnt, 1u) == GRID_SC - 1) {
            g_barCnt = 0;             // reset BEFORE release -> replay-safe
            __threadfence();
            g_barGen = gen + 1;
        } else {
            while (g_barGen == gen) { __nanosleep(64); }
        }
        __threadfence();
    }
    __syncthreads();
}

__global__ void __launch_bounds__(1024)
scan_fused_kernel()
{
    __shared__ unsigned int sh[1024];
    __shared__ unsigned int tb[512];
    int t = threadIdx.x;

    // phase A: per-chunk sums
    for (int c = blockIdx.x; c < NSCAN_BLOCKS; c += GRID_SC) {
        sh[t] = g_cntbuf[c * 1024 + t];
        __syncthreads();
        for (int d = 512; d > 0; d >>= 1) {
            if (t < d) sh[t] += sh[t + d];
            __syncthreads();
        }
        if (t == 0) g_bsum[c] = sh[0];
        __syncthreads();
    }
    grid_barrier_sc();

    // phase B: redundant top scan + per-chunk offsets
    if (t < 512) tb[t] = (t < NSCAN_BLOCKS) ? g_bsum[t] : 0u;
    __syncthreads();
    for (int d = 1; d < 512; d <<= 1) {
        unsigned int add = (t < 512 && t >= d) ? tb[t - d] : 0u;
        __syncthreads();
        if (t < 512) tb[t] += add;
        __syncthreads();
    }
    for (int c = blockIdx.x; c < NSCAN_BLOCKS; c += GRID_SC) {
        int gi = c * 1024 + t;
        unsigned int v = g_cntbuf[gi];
        sh[t] = v;
        __syncthreads();
        for (int d = 1; d < 1024; d <<= 1) {
            unsigned int add = (t >= d) ? sh[t - d] : 0u;
            __syncthreads();
            sh[t] += add;
            __syncthreads();
        }
        unsigned int o = sh[t] - v + ((c > 0) ? tb[c - 1] : 0u);
        g_off[gi] = o;
        g_woff[gi] = o;
        __syncthreads();
    }
}

// ---------------- pass 2: place, 4 records/thread (MLP) -------------------
__global__ void place_kernel()
{
    unsigned int nvalid = g_cntbuf[HW];
    if (nvalid > NPAD) nvalid = NPAD;
    unsigned int t0 = (blockIdx.x * blockDim.x + threadIdx.x) * RPT;
    if (t0 >= nvalid) return;
    int cnt = (nvalid - t0 < RPT) ? (int)(nvalid - t0) : RPT;
    float4 rec[RPT];
#pragma unroll
    for (int q = 0; q < RPT; q++)
        if (q < cnt) rec[q] = g_rec[t0 + q];
#pragma unroll
    for (int q = 0; q < RPT; q++) {
        if (q < cnt) {
            int pid = __float_as_int(rec[q].x);
            unsigned int pos = atomicAdd(&g_woff[pid], 1u);
            if (pos < NPAD)
                g_srec[pos] = make_float4(rec[q].y, rec[q].z, rec[q].w, 0.0f);
        }
    }
}

// ---------------- per-pixel sort (z desc, idx asc) + emit lg --------------
__device__ __forceinline__ bool rec_before(const float4& a, const float4& b)
{
    if (a.x != b.x) return a.x > b.x;                   // z desc
    return __float_as_uint(a.z) < __float_as_uint(b.z); // idx asc
}

__global__ void sortemit_kernel()
{
    int p = blockIdx.x * blockDim.x + threadIdx.x;
    if (p >= HW) return;
    unsigned int s = g_off[p];
    unsigned int k = g_cntbuf[p];
    if (k == 0) return;
    if (k <= KMAX) {
        float4 a[KMAX];
        for (unsigned int i = 0; i < k; i++) a[i] = g_srec[s + i];
        for (unsigned int i = 1; i < k; i++) {
            float4 key = a[i];
            int j = (int)i - 1;
            while (j >= 0 && rec_before(key, a[j])) { a[j + 1] = a[j]; j--; }
            a[j + 1] = key;
        }
        for (unsigned int i = 0; i < k; i++) {
            g_srec[s + i] = a[i];
            g_x[s + i] = log1pf(-a[i].y);
        }
    } else {
        for (unsigned int i = 0; i < k; i++) {
            unsigned int best = i;
            float4 bv = g_srec[s + i];
            for (unsigned int j = i + 1; j < k; j++) {
                float4 cv = g_srec[s + j];
                if (rec_before(cv, bv)) { best = j; bv = cv; }
            }
            if (best != i) {
                float4 tmp = g_srec[s + i];
                g_srec[s + i] = bv;
                g_srec[s + best] = tmp;
            }
            g_x[s + i] = log1pf(-bv.y);
        }
    }
}

// ---------------- scan A: per-chunk tree sum + fused mid scan -------------
__global__ void scan_down_kernel()
{
    __shared__ float sh[2048];
    __shared__ bool isLast;
    int t = threadIdx.x;               // 1024
    int base = blockIdx.x * 2048;
    unsigned int nvalid = g_cntbuf[HW];
    if (nvalid > NPAD) nvalid = NPAD;
    int g0 = base + t, g1 = base + t + 1024;
    sh[t]        = ((unsigned int)g0 < nvalid) ? g_x[g0] : 0.0f;
    sh[t + 1024] = ((unsigned int)g1 < nvalid) ? g_x[g1] : 0.0f;
    __syncthreads();
    for (int size = 1024; size >= 1; size >>= 1) {
        float v = 0.0f;
        if (t < size) v = sh[2 * t] + sh[2 * t + 1];
        __syncthreads();
        if (t < size) sh[t] = v;
        __syncthreads();
    }
    if (t == 0) {
        g_L11[blockIdx.x] = sh[0];
        __threadfence();
        isLast = (atomicAdd(&g_tick, 1u) == NCHUNK - 1);
    }
    __syncthreads();
    if (!isLast) return;

    // fused mid scan (levels 12..19 + S11), last block only
    if (t == 0) g_tick = 0;   // reset for next graph replay
    float* Lv = sh;           // [0..510]
    float* Sv = sh + 512;     // [0..510]
    if (t < 256) Lv[t] = g_L11[t];
    __syncthreads();
    int off = 0, size = 256;
    for (int d = 0; d < 8; d++) {
        int noff = off + size, nsz = size >> 1;
        if (t < nsz) Lv[noff + t] = Lv[off + 2 * t] + Lv[off + 2 * t + 1];
        __syncthreads();
        off = noff; size = nsz;
    }
    if (t == 0) Sv[510] = Lv[510];
    __syncthreads();
    for (int d = 0; d < 8; d++) {
        int sz = 2 << d;
        off -= sz;
        int poff = off + sz;
        if (t < sz) {
            float v;
            if (t == 0)      v = Lv[off];
            else if (t & 1)  v = Sv[poff + ((t - 1) >> 1)];
            else             v = Sv[poff + (t >> 1) - 1] + Lv[off + t];
            Sv[off + t] = v;
        }
        __syncthreads();
    }
    if (t < 256) g_S11[t] = Sv[t];
}

// ---------------- scan C: up-sweep, writes S (level 0) --------------------
__global__ void scan_up_kernel()
{
    __shared__ float Lb[4094];
    __shared__ float Sa[2048];
    __shared__ float Sb[1024];
    int t = threadIdx.x;               // 1024
    int b = blockIdx.x;
    int base = b * 2048;
    unsigned int nvalid = g_cntbuf[HW];
    if (nvalid > NPAD) nvalid = NPAD;
    int g0 = base + t, g1 = base + t + 1024;
    Lb[t]        = ((unsigned int)g0 < nvalid) ? g_x[g0] : 0.0f;
    Lb[t + 1024] = ((unsigned int)g1 < nvalid) ? g_x[g1] : 0.0f;
    __syncthreads();
    int off = 0, size = 2048;
    for (int d = 1; d <= 10; d++) {
        int noff = off + size, nsz = size >> 1;
        for (int j = t; j < nsz; j += 1024)
            Lb[noff + j] = Lb[off + 2 * j] + Lb[off + 2 * j + 1];
        __syncthreads();
        off = noff; size = nsz;
    }
    float bound = (b > 0) ? g_S11[b - 1] : 0.0f;
    if (t == 0) {
        Sa[0] = (b == 0) ? Lb[off] : bound + Lb[off];
        Sa[1] = g_S11[b];
    }
    __syncthreads();
    for (int d = 9; d >= 0; d--) {
        int sz = 2048 >> d;
        off -= sz;
        float* Sprev = (d & 1) ? Sa : Sb;
        float* Scur  = (d & 1) ? Sb : Sa;
        for (int j = t; j < sz; j += 1024) {
            float v;
            if (j == 0)      v = (b == 0) ? Lb[off] : bound + Lb[off];
            else if (j & 1)  v = Sprev[(j - 1) >> 1];
            else             v = Sprev[(j >> 1) - 1] + Lb[off + j];
            Scur[j] = v;
        }
        __syncthreads();
    }
    g_S[base + t] = Sa[t];
    g_S[base + t + 1024] = Sa[t + 1024];
}

// ---------------- render ----------------
__global__ void render_kernel(const float* __restrict__ feats,
                              float* __restrict__ out)
{
    int p = blockIdx.x * blockDim.x + threadIdx.x;
    if (p >= HW) return;
    unsigned int s = g_off[p];
    unsigned int k = g_cntbuf[p];

    float img0 = 0.0f, img1 = 0.0f, img2 = 0.0f;
    float dep = 0.0f;
    float Lsum = 0.0f;

    float c_end = (k > 0) ? g_S[s + k - 1] : 0.0f;
    for (unsigned int i = 0; i < k; i++) {
        float4 r = g_srec[s + i];
        float T = expf(c_end - g_S[s + i]);
        float contrib = r.y * T;
        unsigned int idx = __float_as_uint(r.z);
        img0 += contrib * feats[3 * idx + 0];
        img1 += contrib * feats[3 * idx + 1];
        img2 += contrib * feats[3 * idx + 2];
        dep  += contrib * r.x;
        Lsum += g_x[s + i];
    }

    out[0 * HW + p] = img0;
    out[1 * HW + p] = img1;
    out[2 * HW + p] = img2;
    out[3 * HW + p] = dep;
    out[4 * HW + p] = 1.0f - expf(Lsum);
}

// ---------------- launch ----------------
extern "C" void kernel_launch(void* const* d_in, const int* in_sizes, int n_in,
                              void* d_out, int out_size)
{
    const float* means = (const float*)d_in[0];
    const float* opac  = (const float*)d_in[1];
    const float* feats = (const float*)d_in[2];
    const float* pose  = (const float*)d_in[3];
    float* out = (float*)d_out;

    int n = in_sizes[0] / 3;

    void* cnt_addr = nullptr; cudaGetSymbolAddress(&cnt_addr, g_cntbuf);
    cudaMemsetAsync(cnt_addr, 0, (HW + 1) * sizeof(unsigned int), 0);

    int npt = (n + PPT - 1) / PPT;
    project_count_kernel<<<(npt + PRJ_TPB - 1) / PRJ_TPB, PRJ_TPB>>>(
        (const float4*)means, means, opac, pose, n);
    scan_fused_kernel<<<GRID_SC, 1024>>>();
    place_kernel<<<NPAD / (256 * RPT), 256>>>();
    sortemit_kernel<<<(HW + 255) / 256, 256>>>();
    scan_down_kernel<<<NCHUNK, 1024>>>();
    scan_up_kernel<<<NCHUNK, 1024>>>();
    render_kernel<<<(HW + 255) / 256, 256>>>(feats, out);
}

// round 9
// speedup vs baseline: 1.2995x; 1.1547x over previous
#include <cuda_runtime.h>
#include <cuda_bf16.h>
#include <math.h>

#define IMG_H 512
#define IMG_W 640
#define HW (IMG_H * IMG_W)            // 327680
#define FXc 500.0f
#define FYc 500.0f
#define CXc 320.0f
#define CYc 256.0f

#define SCAN_BLK 1024
#define NSCAN_BLOCKS 320              // HW / 1024
#define NPAD 524288                   // 2^19 >= n_valid (~345k)
#define NCHUNK 256                    // NPAD / 2048

#define PRJ_TPB 256
#define PRJ_WARPS (PRJ_TPB / 32)
#define PPT 4

typedef unsigned long long u64;
typedef unsigned int u32;

// ---------------- device scratch ----------------
__device__ u32 g_cntbuf[HW + 1];   // [HW] = nvalid append counter
__device__ u32 g_off[HW];
__device__ u32 g_woff[HW];
__device__ u32 g_bsum[NSCAN_BLOCKS];
__device__ u32 g_tick;             // scan_down last-block ticket (self-reset)

__device__ u32 g_rpid[NPAD];       // unordered: pixel id per record
__device__ u64 g_rkey[NPAD];       // unordered: packed (z desc, idx) key
__device__ u64 g_key[NPAD];        // binned (then sorted in place)

__device__ float g_x[NPAD];        // lg at sorted positions
__device__ float g_S[NPAD];        // inclusive scan, assoc-scan rounding replicated
__device__ float g_L11[NCHUNK];
__device__ float g_S11[NCHUNK];

// key: ascending u64 sort == (z desc, idx asc). z>0 so float bits monotonic.
__device__ __forceinline__ u64 pack_key(float z, u32 idx)
{
    return ((u64)(0xFFFFFFFFu - __float_as_uint(z)) << 32) | (u64)idx;
}
__device__ __forceinline__ float key_z(u64 k)
{
    return __uint_as_float(0xFFFFFFFFu - (u32)(k >> 32));
}

// ---------------- pass 1: project 4 pts/thread (R1-verified rounding) -----
__global__ void project_count_kernel(const float4* __restrict__ means4,
                                     const float* __restrict__ means,
                                     const float* __restrict__ opac,
                                     const float* __restrict__ pose, int n)
{
    __shared__ u32 wcnt[PRJ_WARPS];
    __shared__ u32 woffs[PRJ_WARPS];
    __shared__ u32 sbase;

    int tbase = (blockIdx.x * blockDim.x + threadIdx.x) * PPT;
    int lane = threadIdx.x & 31;
    int warp = threadIdx.x >> 5;

    float m[PPT][3];
    bool valid[PPT];
    int pid[PPT];
    float zv[PPT];
    u32 cnt = 0;

#pragma unroll
    for (int q = 0; q < PPT; q++) { m[q][0] = 0.0f; m[q][1] = 0.0f; m[q][2] = -1.0f; }
    if (tbase + PPT <= n) {
        int v = tbase >> 2;
        float4 a = means4[3 * v + 0];
        float4 b = means4[3 * v + 1];
        float4 c = means4[3 * v + 2];
        m[0][0] = a.x; m[0][1] = a.y; m[0][2] = a.z;
        m[1][0] = a.w; m[1][1] = b.x; m[1][2] = b.y;
        m[2][0] = b.z; m[2][1] = b.w; m[2][2] = c.x;
        m[3][0] = c.y; m[3][1] = c.z; m[3][2] = c.w;
    } else if (tbase < n) {
        for (int q = 0; q < PPT; q++)
            if (tbase + q < n) {
                m[q][0] = means[3 * (tbase + q) + 0];
                m[q][1] = means[3 * (tbase + q) + 1];
                m[q][2] = means[3 * (tbase + q) + 2];
            }
    }

#pragma unroll
    for (int q = 0; q < PPT; q++) {
        float m0 = m[q][0], m1 = m[q][1], m2 = m[q][2];
        // pose is identity: exact regardless of order
        float pc0 = m0 * pose[0] + m1 * pose[1] + m2 * pose[2]  + pose[3];
        float pc1 = m0 * pose[4] + m1 * pose[5] + m2 * pose[6]  + pose[7];
        float z   = m0 * pose[8] + m1 * pose[9] + m2 * pose[10] + pose[11];
        // IEEE rn div/mul/add, NO fma (matches reference; measured best)
        float x = __fadd_rn(__fmul_rn(__fdiv_rn(pc0, z), FXc), CXc);
        float y = __fadd_rn(__fmul_rn(__fdiv_rn(pc1, z), FYc), CYc);
        bool ok = (tbase + q < n) && (x >= 0.0f) && (x < (float)IMG_W) &&
                  (y >= 0.0f) && (y < (float)IMG_H) && (z > 0.0f);
        valid[q] = ok;
        if (ok) {
            pid[q] = (int)floorf(y) * IMG_W + (int)floorf(x);
            zv[q] = z;
            cnt++;
        }
    }

    u32 pre = cnt;
#pragma unroll
    for (int d = 1; d < 32; d <<= 1) {
        u32 u = __shfl_up_sync(0xffffffffu, pre, d);
        if (lane >= d) pre += u;
    }
    if (lane == 31) wcnt[warp] = pre;
    __syncthreads();
    if (threadIdx.x == 0) {
        u32 run = 0;
#pragma unroll
        for (int wi = 0; wi < PRJ_WARPS; wi++) { woffs[wi] = run; run += wcnt[wi]; }
        sbase = (run > 0) ? atomicAdd(&g_cntbuf[HW], run) : 0u;
    }
    __syncthreads();

    u32 pos = sbase + woffs[warp] + (pre - cnt);
#pragma unroll
    for (int q = 0; q < PPT; q++) {
        if (valid[q]) {
            atomicAdd(&g_cntbuf[pid[q]], 1u);
            if (pos < NPAD) {
                g_rpid[pos] = (u32)pid[q];
                g_rkey[pos] = pack_key(zv[q], (u32)(tbase + q));
            }
            pos++;
        }
    }
}

// ---------------- offset scan: block sums ----------------
__global__ void scan_reduce_kernel()
{
    __shared__ u32 sh[SCAN_BLK];
    int t = threadIdx.x;
    sh[t] = g_cntbuf[blockIdx.x * SCAN_BLK + t];
    __syncthreads();
    for (int d = SCAN_BLK / 2; d > 0; d >>= 1) {
        if (t < d) sh[t] += sh[t + d];
        __syncthreads();
    }
    if (t == 0) g_bsum[blockIdx.x] = sh[0];
}

// ---------------- offset scan: full (redundant top scan per block) --------
__global__ void scan_offsets_kernel()
{
    __shared__ u32 sh[SCAN_BLK];
    __shared__ u32 tb[512];
    int t = threadIdx.x;
    int gi = blockIdx.x * SCAN_BLK + t;
    u32 v = g_cntbuf[gi];
    sh[t] = v;
    if (t < 512) tb[t] = (t < NSCAN_BLOCKS) ? g_bsum[t] : 0u;
    __syncthreads();
#pragma unroll
    for (int d = 1; d < SCAN_BLK; d <<= 1) {
        u32 add = (t >= d) ? sh[t - d] : 0u;
        u32 addt = (t < 512 && t >= d) ? tb[t - d] : 0u;
        __syncthreads();
        sh[t] += add;
        if (t < 512 && d < 512) tb[t] += addt;
        __syncthreads();
    }
    u32 bpref = (blockIdx.x > 0) ? tb[blockIdx.x - 1] : 0u;
    u32 o = sh[t] - v + bpref;
    g_off[gi] = o;
    g_woff[gi] = o;
}

// ---------------- pass 2: place keys into bins ----------------
__global__ void place_kernel()
{
    u32 r = blockIdx.x * blockDim.x + threadIdx.x;
    if (r >= g_cntbuf[HW] || r >= NPAD) return;
    u32 pid = g_rpid[r];
    u64 key = g_rkey[r];
    u32 pos = atomicAdd(&g_woff[pid], 1u);
    if (pos < NPAD) g_key[pos] = key;
}

// ---------------- per-pixel sort via register sorting networks ------------
#define CSW(a, b) { u64 _lo = (a) < (b) ? (a) : (b); \
                    u64 _hi = (a) < (b) ? (b) : (a); (a) = _lo; (b) = _hi; }

__global__ void sortemit_kernel(const float* __restrict__ opac)
{
    int p = blockIdx.x * blockDim.x + threadIdx.x;
    if (p >= HW) return;
    u32 s = g_off[p];
    u32 k = g_cntbuf[p];
    if (k == 0) return;

    if (k == 1) {
        u64 key = g_key[s];
        g_x[s] = log1pf(-opac[(u32)key]);
        return;
    }
    if (k <= 4) {
        u64 a[4];
#pragma unroll
        for (int i = 0; i < 4; i++)
            a[i] = ((u32)i < k) ? g_key[s + i] : ~0ull;
        CSW(a[0], a[1]); CSW(a[2], a[3]);
        CSW(a[0], a[2]); CSW(a[1], a[3]);
        CSW(a[1], a[2]);
#pragma unroll
        for (int i = 0; i < 4; i++)
            if ((u32)i < k) {
                g_key[s + i] = a[i];
                g_x[s + i] = log1pf(-opac[(u32)a[i]]);
            }
        return;
    }
    if (k <= 8) {
        u64 a[8];
#pragma unroll
        for (int i = 0; i < 8; i++)
            a[i] = ((u32)i < k) ? g_key[s + i] : ~0ull;
        // Batcher odd-even merge sort, 8 inputs, 19 CEs
        CSW(a[0], a[1]); CSW(a[2], a[3]); CSW(a[4], a[5]); CSW(a[6], a[7]);
        CSW(a[0], a[2]); CSW(a[1], a[3]); CSW(a[4], a[6]); CSW(a[5], a[7]);
        CSW(a[1], a[2]); CSW(a[5], a[6]);
        CSW(a[0], a[4]); CSW(a[1], a[5]); CSW(a[2], a[6]); CSW(a[3], a[7]);
        CSW(a[2], a[4]); CSW(a[3], a[5]);
        CSW(a[1], a[2]); CSW(a[3], a[4]); CSW(a[5], a[6]);
#pragma unroll
        for (int i = 0; i < 8; i++)
            if ((u32)i < k) {
                g_key[s + i] = a[i];
                g_x[s + i] = log1pf(-opac[(u32)a[i]]);
            }
        return;
    }
    if (k <= 16) {
        u64 a[16];
#pragma unroll
        for (int i = 0; i < 16; i++)
            a[i] = ((u32)i < k) ? g_key[s + i] : ~0ull;
        // bitonic sort, fully unrolled, constant indices
#pragma unroll
        for (int kk = 2; kk <= 16; kk <<= 1) {
#pragma unroll
            for (int j = kk >> 1; j > 0; j >>= 1) {
#pragma unroll
                for (int i = 0; i < 16; i++) {
                    int l = i ^ j;
                    if (l > i) {
                        bool up = ((i & kk) == 0);
                        u64 x = a[i], y = a[l];
                        bool sw = up ? (x > y) : (x < y);
                        a[i] = sw ? y : x;
                        a[l] = sw ? x : y;
                    }
                }
            }
        }
#pragma unroll
        for (int i = 0; i < 16; i++)
            if ((u32)i < k) {
                g_key[s + i] = a[i];
                g_x[s + i] = log1pf(-opac[(u32)a[i]]);
            }
        return;
    }
    // fallback: global selection sort (vanishingly rare)
    for (u32 i = 0; i < k; i++) {
        u32 best = i;
        u64 bv = g_key[s + i];
        for (u32 j = i + 1; j < k; j++) {
            u64 cv = g_key[s + j];
            if (cv < bv) { best = j; bv = cv; }
        }
        if (best != i) {
            u64 tmp = g_key[s + i];
            g_key[s + i] = bv;
            g_key[s + best] = tmp;
        }
        g_x[s + i] = log1pf(-opac[(u32)bv]);
    }
}

// ---------------- scan A: per-chunk tree sum + fused mid scan -------------
__global__ void scan_down_kernel()
{
    __shared__ float sh[2048];
    __shared__ bool isLast;
    int t = threadIdx.x;               // 1024
    int base = blockIdx.x * 2048;
    u32 nvalid = g_cntbuf[HW];
    if (nvalid > NPAD) nvalid = NPAD;
    int g0 = base + t, g1 = base + t + 1024;
    sh[t]        = ((u32)g0 < nvalid) ? g_x[g0] : 0.0f;
    sh[t + 1024] = ((u32)g1 < nvalid) ? g_x[g1] : 0.0f;
    __syncthreads();
    for (int size = 1024; size >= 1; size >>= 1) {
        float v = 0.0f;
        if (t < size) v = sh[2 * t] + sh[2 * t + 1];
        __syncthreads();
        if (t < size) sh[t] = v;
        __syncthreads();
    }
    if (t == 0) {
        g_L11[blockIdx.x] = sh[0];
        __threadfence();
        isLast = (atomicAdd(&g_tick, 1u) == NCHUNK - 1);
    }
    __syncthreads();
    if (!isLast) return;

    // fused mid scan (levels 12..19 + S11), last block only
    if (t == 0) g_tick = 0;   // reset for next graph replay
    float* Lv = sh;           // [0..510]
    float* Sv = sh + 512;     // [0..510]
    if (t < 256) Lv[t] = g_L11[t];
    __syncthreads();
    int off = 0, size = 256;
    for (int d = 0; d < 8; d++) {
        int noff = off + size, nsz = size >> 1;
        if (t < nsz) Lv[noff + t] = Lv[off + 2 * t] + Lv[off + 2 * t + 1];
        __syncthreads();
        off = noff; size = nsz;
    }
    if (t == 0) Sv[510] = Lv[510];
    __syncthreads();
    for (int d = 0; d < 8; d++) {
        int sz = 2 << d;
        off -= sz;
        int poff = off + sz;
        if (t < sz) {
            float v;
            if (t == 0)      v = Lv[off];
            else if (t & 1)  v = Sv[poff + ((t - 1) >> 1)];
            else             v = Sv[poff + (t >> 1) - 1] + Lv[off + t];
            Sv[off + t] = v;
        }
        __syncthreads();
    }
    if (t < 256) g_S11[t] = Sv[t];
}

// ---------------- scan C: up-sweep, writes S (level 0) --------------------
__global__ void scan_up_kernel()
{
    __shared__ float Lb[4094];
    __shared__ float Sa[2048];
    __shared__ float Sb[1024];
    int t = threadIdx.x;               // 1024
    int b = blockIdx.x;
    int base = b * 2048;
    u32 nvalid = g_cntbuf[HW];
    if (nvalid > NPAD) nvalid = NPAD;
    int g0 = base + t, g1 = base + t + 1024;
    Lb[t]        = ((u32)g0 < nvalid) ? g_x[g0] : 0.0f;
    Lb[t + 1024] = ((u32)g1 < nvalid) ? g_x[g1] : 0.0f;
    __syncthreads();
    int off = 0, size = 2048;
    for (int d = 1; d <= 10; d++) {
        int noff = off + size, nsz = size >> 1;
        for (int j = t; j < nsz; j += 1024)
            Lb[noff + j] = Lb[off + 2 * j] + Lb[off + 2 * j + 1];
        __syncthreads();
        off = noff; size = nsz;
    }
    float bound = (b > 0) ? g_S11[b - 1] : 0.0f;
    if (t == 0) {
        Sa[0] = (b == 0) ? Lb[off] : bound + Lb[off];
        Sa[1] = g_S11[b];
    }
    __syncthreads();
    for (int d = 9; d >= 0; d--) {
        int sz = 2048 >> d;
        off -= sz;
        float* Sprev = (d & 1) ? Sa : Sb;
        float* Scur  = (d & 1) ? Sb : Sa;
        for (int j = t; j < sz; j += 1024) {
            float v;
            if (j == 0)      v = (b == 0) ? Lb[off] : bound + Lb[off];
            else if (j & 1)  v = Sprev[(j - 1) >> 1];
            else             v = Sprev[(j >> 1) - 1] + Lb[off + j];
            Scur[j] = v;
        }
        __syncthreads();
    }
    g_S[base + t] = Sa[t];
    g_S[base + t + 1024] = Sa[t + 1024];
}

// ---------------- render ----------------
__global__ void render_kernel(const float* __restrict__ opac,
                              const float* __restrict__ feats,
                              float* __restrict__ out)
{
    int p = blockIdx.x * blockDim.x + threadIdx.x;
    if (p >= HW) return;
    u32 s = g_off[p];
    u32 k = g_cntbuf[p];

    float img0 = 0.0f, img1 = 0.0f, img2 = 0.0f;
    float dep = 0.0f;
    float Lsum = 0.0f;

    float c_end = (k > 0) ? g_S[s + k - 1] : 0.0f;
    for (u32 i = 0; i < k; i++) {
        u64 key = g_key[s + i];
        u32 idx = (u32)key;
        float z = key_z(key);
        float w = opac[idx];
        float T = expf(c_end - g_S[s + i]);
        float contrib = w * T;
        img0 += contrib * feats[3 * idx + 0];
        img1 += contrib * feats[3 * idx + 1];
        img2 += contrib * feats[3 * idx + 2];
        dep  += contrib * z;
        Lsum += g_x[s + i];
    }

    out[0 * HW + p] = img0;
    out[1 * HW + p] = img1;
    out[2 * HW + p] = img2;
    out[3 * HW + p] = dep;
    out[4 * HW + p] = 1.0f - expf(Lsum);
}

// ---------------- launch ----------------
extern "C" void kernel_launch(void* const* d_in, const int* in_sizes, int n_in,
                              void* d_out, int out_size)
{
    const float* means = (const float*)d_in[0];
    const float* opac  = (const float*)d_in[1];
    const float* feats = (const float*)d_in[2];
    const float* pose  = (const float*)d_in[3];
    float* out = (float*)d_out;

    int n = in_sizes[0] / 3;

    void* cnt_addr = nullptr; cudaGetSymbolAddress(&cnt_addr, g_cntbuf);
    cudaMemsetAsync(cnt_addr, 0, (HW + 1) * sizeof(u32), 0);

    int npt = (n + PPT - 1) / PPT;
    project_count_kernel<<<(npt + PRJ_TPB - 1) / PRJ_TPB, PRJ_TPB>>>(
        (const float4*)means, means, opac, pose, n);
    scan_reduce_kernel<<<NSCAN_BLOCKS, SCAN_BLK>>>();
    scan_offsets_kernel<<<NSCAN_BLOCKS, SCAN_BLK>>>();
    place_kernel<<<NPAD / 256, 256>>>();
    sortemit_kernel<<<(HW + 255) / 256, 256>>>(opac);
    scan_down_kernel<<<NCHUNK, 1024>>>();
    scan_up_kernel<<<NCHUNK, 1024>>>();
    render_kernel<<<(HW + 255) / 256, 256>>>(opac, feats, out);
}

// round 10
// speedup vs baseline: 1.3702x; 1.0544x over previous
#include <cuda_runtime.h>
#include <cuda_bf16.h>
#include <math.h>

#define IMG_H 512
#define IMG_W 640
#define HW (IMG_H * IMG_W)            // 327680
#define FXc 500.0f
#define FYc 500.0f
#define CXc 320.0f
#define CYc 256.0f

#define SCAN_BLK 1024
#define NSCAN_BLOCKS 320              // HW / 1024
#define NPAD 524288                   // 2^19 >= n_valid (~345k)
#define NCHUNK 256                    // NPAD / 2048

#define PRJ_TPB 256
#define PRJ_WARPS (PRJ_TPB / 32)
#define PPT 4

typedef unsigned long long u64;
typedef unsigned int u32;

// ---------------- device scratch ----------------
// g_cntbuf layout: [0..HW) per-pixel counts | [HW] nvalid | [HW+1] pad |
//                  [HW+2 .. HW+2+2*NSCAN_BLOCKS) lookback descriptors (u64)
#define CNT_WORDS (HW + 2 + 2 * NSCAN_BLOCKS)
__device__ u32 g_cntbuf[CNT_WORDS];
__device__ u32 g_off[HW];
__device__ u32 g_woff[HW];
__device__ u32 g_tick;             // scan_down last-block ticket (self-reset)

__device__ u32 g_rpid[NPAD];       // unordered: pixel id per record
__device__ u64 g_rkey[NPAD];       // unordered: packed (z desc, idx) key
__device__ u64 g_key[NPAD];        // binned (then sorted in place)

__device__ float g_x[NPAD];        // lg at sorted positions
__device__ float g_S[NPAD];        // inclusive scan, assoc-scan rounding replicated
__device__ float g_L11[NCHUNK];
__device__ float g_S11[NCHUNK];

// key: ascending u64 sort == (z desc, idx asc). z>0 so float bits monotonic.
__device__ __forceinline__ u64 pack_key(float z, u32 idx)
{
    return ((u64)(0xFFFFFFFFu - __float_as_uint(z)) << 32) | (u64)idx;
}
__device__ __forceinline__ float key_z(u64 k)
{
    return __uint_as_float(0xFFFFFFFFu - (u32)(k >> 32));
}

// ---------------- pass 1: project 4 pts/thread (R1-verified rounding) -----
__global__ void project_count_kernel(const float4* __restrict__ means4,
                                     const float* __restrict__ means,
                                     const float* __restrict__ opac,
                                     const float* __restrict__ pose, int n)
{
    __shared__ u32 wcnt[PRJ_WARPS];
    __shared__ u32 woffs[PRJ_WARPS];
    __shared__ u32 sbase;

    int tbase = (blockIdx.x * blockDim.x + threadIdx.x) * PPT;
    int lane = threadIdx.x & 31;
    int warp = threadIdx.x >> 5;

    float m[PPT][3];
    bool valid[PPT];
    int pid[PPT];
    float zv[PPT];
    u32 cnt = 0;

#pragma unroll
    for (int q = 0; q < PPT; q++) { m[q][0] = 0.0f; m[q][1] = 0.0f; m[q][2] = -1.0f; }
    if (tbase + PPT <= n) {
        int v = tbase >> 2;
        float4 a = means4[3 * v + 0];
        float4 b = means4[3 * v + 1];
        float4 c = means4[3 * v + 2];
        m[0][0] = a.x; m[0][1] = a.y; m[0][2] = a.z;
        m[1][0] = a.w; m[1][1] = b.x; m[1][2] = b.y;
        m[2][0] = b.z; m[2][1] = b.w; m[2][2] = c.x;
        m[3][0] = c.y; m[3][1] = c.z; m[3][2] = c.w;
    } else if (tbase < n) {
        for (int q = 0; q < PPT; q++)
            if (tbase + q < n) {
                m[q][0] = means[3 * (tbase + q) + 0];
                m[q][1] = means[3 * (tbase + q) + 1];
                m[q][2] = means[3 * (tbase + q) + 2];
            }
    }

#pragma unroll
    for (int q = 0; q < PPT; q++) {
        float m0 = m[q][0], m1 = m[q][1], m2 = m[q][2];
        // pose is identity: exact regardless of order
        float pc0 = m0 * pose[0] + m1 * pose[1] + m2 * pose[2]  + pose[3];
        float pc1 = m0 * pose[4] + m1 * pose[5] + m2 * pose[6]  + pose[7];
        float z   = m0 * pose[8] + m1 * pose[9] + m2 * pose[10] + pose[11];
        // IEEE rn div/mul/add, NO fma (matches reference; measured best)
        float x = __fadd_rn(__fmul_rn(__fdiv_rn(pc0, z), FXc), CXc);
        float y = __fadd_rn(__fmul_rn(__fdiv_rn(pc1, z), FYc), CYc);
        bool ok = (tbase + q < n) && (x >= 0.0f) && (x < (float)IMG_W) &&
                  (y >= 0.0f) && (y < (float)IMG_H) && (z > 0.0f);
        valid[q] = ok;
        if (ok) {
            pid[q] = (int)floorf(y) * IMG_W + (int)floorf(x);
            zv[q] = z;
            cnt++;
        }
    }

    u32 pre = cnt;
#pragma unroll
    for (int d = 1; d < 32; d <<= 1) {
        u32 u = __shfl_up_sync(0xffffffffu, pre, d);
        if (lane >= d) pre += u;
    }
    if (lane == 31) wcnt[warp] = pre;
    __syncthreads();
    if (threadIdx.x == 0) {
        u32 run = 0;
#pragma unroll
        for (int wi = 0; wi < PRJ_WARPS; wi++) { woffs[wi] = run; run += wcnt[wi]; }
        sbase = (run > 0) ? atomicAdd(&g_cntbuf[HW], run) : 0u;
    }
    __syncthreads();

    u32 pos = sbase + woffs[warp] + (pre - cnt);
#pragma unroll
    for (int q = 0; q < PPT; q++) {
        if (valid[q]) {
            atomicAdd(&g_cntbuf[pid[q]], 1u);
            if (pos < NPAD) {
                g_rpid[pos] = (u32)pid[q];
                g_rkey[pos] = pack_key(zv[q], (u32)(tbase + q));
            }
            pos++;
        }
    }
}

// ---------------- offset scan: single pass, decoupled lookback ------------
// descriptor: (status << 32) | value; status 0=empty, 1=aggregate, 2=inclusive
__global__ void __launch_bounds__(SCAN_BLK)
scan_offsets_kernel()
{
    __shared__ u32 sh[SCAN_BLK];
    __shared__ u32 sprefix;
    u64* desc = (u64*)&g_cntbuf[HW + 2];

    int t = threadIdx.x;
    int b = blockIdx.x;
    int gi = b * SCAN_BLK + t;
    u32 v = g_cntbuf[gi];
    sh[t] = v;
    __syncthreads();
#pragma unroll
    for (int d = 1; d < SCAN_BLK; d <<= 1) {
        u32 add = (t >= d) ? sh[t - d] : 0u;
        __syncthreads();
        sh[t] += add;
        __syncthreads();
    }
    u32 agg = sh[SCAN_BLK - 1];

    if (t == 0) {
        u64 pub = (b == 0) ? ((2ull << 32) | (u64)agg)
                           : ((1ull << 32) | (u64)agg);
        atomicExch((unsigned long long*)&desc[b], pub);
        if (b == 0) sprefix = 0u;
    }

    // warp 0: backward lookback over predecessors (only lower bids -> safe)
    if (b > 0 && t < 32) {
        u32 running = 0;
        int offset = b;
        while (true) {
            int j = offset - 1 - t;
            u64 d;
            if (j >= 0) {
                do {
                    d = atomicAdd((unsigned long long*)&desc[j], 0ull);
                } while ((u32)(d >> 32) == 0u);
            } else {
                d = (2ull << 32);     // virtual inclusive 0 before block 0
            }
            u32 status = (u32)(d >> 32);
            u32 val = (u32)d;
            u32 ballot = __ballot_sync(0xffffffffu, status == 2u);
            if (ballot) {
                int l2 = __ffs(ballot) - 1;   // nearest inclusive going back
                u32 contrib = (t <= l2) ? val : 0u;
#pragma unroll
                for (int o = 16; o > 0; o >>= 1)
                    contrib += __shfl_down_sync(0xffffffffu, contrib, o);
                if (t == 0) running += contrib;
                break;
            } else {
                u32 contrib = val;
#pragma unroll
                for (int o = 16; o > 0; o >>= 1)
                    contrib += __shfl_down_sync(0xffffffffu, contrib, o);
                if (t == 0) running += contrib;
                offset -= 32;
            }
        }
        if (t == 0) {
            sprefix = running;
            atomicExch((unsigned long long*)&desc[b],
                       (2ull << 32) | (u64)(running + agg));
        }
    }
    __syncthreads();

    u32 o = sh[t] - v + sprefix;
    g_off[gi] = o;
    g_woff[gi] = o;
}

// ---------------- pass 2: place keys, 2 records/thread (MLP) --------------
__global__ void place_kernel()
{
    u32 nvalid = g_cntbuf[HW];
    if (nvalid > NPAD) nvalid = NPAD;
    u32 r0 = (blockIdx.x * blockDim.x + threadIdx.x) * 2;
    if (r0 >= nvalid) return;
    bool h1 = (r0 + 1 < nvalid);
    u32 pid0 = g_rpid[r0];
    u32 pid1 = h1 ? g_rpid[r0 + 1] : 0u;
    u64 key0 = g_rkey[r0];
    u64 key1 = h1 ? g_rkey[r0 + 1] : 0ull;
    u32 pos0 = atomicAdd(&g_woff[pid0], 1u);
    u32 pos1 = h1 ? atomicAdd(&g_woff[pid1], 1u) : 0u;
    if (pos0 < NPAD) g_key[pos0] = key0;
    if (h1 && pos1 < NPAD) g_key[pos1] = key1;
}

// ---------------- per-pixel sort via register sorting networks ------------
#define CSW(a, b) { u64 _lo = (a) < (b) ? (a) : (b); \
                    u64 _hi = (a) < (b) ? (b) : (a); (a) = _lo; (b) = _hi; }

__global__ void sortemit_kernel(const float* __restrict__ opac)
{
    int p = blockIdx.x * blockDim.x + threadIdx.x;
    if (p >= HW) return;
    u32 s = g_off[p];
    u32 k = g_cntbuf[p];
    if (k == 0) return;

    if (k == 1) {
        u64 key = g_key[s];
        g_x[s] = log1pf(-opac[(u32)key]);
        return;
    }
    if (k <= 4) {
        u64 a[4];
#pragma unroll
        for (int i = 0; i < 4; i++)
            a[i] = ((u32)i < k) ? g_key[s + i] : ~0ull;
        CSW(a[0], a[1]); CSW(a[2], a[3]);
        CSW(a[0], a[2]); CSW(a[1], a[3]);
        CSW(a[1], a[2]);
#pragma unroll
        for (int i = 0; i < 4; i++)
            if ((u32)i < k) {
                g_key[s + i] = a[i];
                g_x[s + i] = log1pf(-opac[(u32)a[i]]);
            }
        return;
    }
    if (k <= 8) {
        u64 a[8];
#pragma unroll
        for (int i = 0; i < 8; i++)
            a[i] = ((u32)i < k) ? g_key[s + i] : ~0ull;
        CSW(a[0], a[1]); CSW(a[2], a[3]); CSW(a[4], a[5]); CSW(a[6], a[7]);
        CSW(a[0], a[2]); CSW(a[1], a[3]); CSW(a[4], a[6]); CSW(a[5], a[7]);
        CSW(a[1], a[2]); CSW(a[5], a[6]);
        CSW(a[0], a[4]); CSW(a[1], a[5]); CSW(a[2], a[6]); CSW(a[3], a[7]);
        CSW(a[2], a[4]); CSW(a[3], a[5]);
        CSW(a[1], a[2]); CSW(a[3], a[4]); CSW(a[5], a[6]);
#pragma unroll
        for (int i = 0; i < 8; i++)
            if ((u32)i < k) {
                g_key[s + i] = a[i];
                g_x[s + i] = log1pf(-opac[(u32)a[i]]);
            }
        return;
    }
    if (k <= 16) {
        u64 a[16];
#pragma unroll
        for (int i = 0; i < 16; i++)
            a[i] = ((u32)i < k) ? g_key[s + i] : ~0ull;
#pragma unroll
        for (int kk = 2; kk <= 16; kk <<= 1) {
#pragma unroll
            for (int j = kk >> 1; j > 0; j >>= 1) {
#pragma unroll
                for (int i = 0; i < 16; i++) {
                    int l = i ^ j;
                    if (l > i) {
                        bool up = ((i & kk) == 0);
                        u64 x = a[i], y = a[l];
                        bool sw = up ? (x > y) : (x < y);
                        a[i] = sw ? y : x;
                        a[l] = sw ? x : y;
                    }
                }
            }
        }
#pragma unroll
        for (int i = 0; i < 16; i++)
            if ((u32)i < k) {
                g_key[s + i] = a[i];
                g_x[s + i] = log1pf(-opac[(u32)a[i]]);
            }
        return;
    }
    // fallback: global selection sort (vanishingly rare)
    for (u32 i = 0; i < k; i++) {
        u32 best = i;
        u64 bv = g_key[s + i];
        for (u32 j = i + 1; j < k; j++) {
            u64 cv = g_key[s + j];
            if (cv < bv) { best = j; bv = cv; }
        }
        if (best != i) {
            u64 tmp = g_key[s + i];
            g_key[s + i] = bv;
            g_key[s + best] = tmp;
        }
        g_x[s + i] = log1pf(-opac[(u32)bv]);
    }
}

// ---------------- scan A: per-chunk tree sum + fused mid scan -------------
__global__ void scan_down_kernel()
{
    __shared__ float sh[2048];
    __shared__ bool isLast;
    int t = threadIdx.x;               // 1024
    int base = blockIdx.x * 2048;
    u32 nvalid = g_cntbuf[HW];
    if (nvalid > NPAD) nvalid = NPAD;
    int g0 = base + t, g1 = base + t + 1024;
    sh[t]        = ((u32)g0 < nvalid) ? g_x[g0] : 0.0f;
    sh[t + 1024] = ((u32)g1 < nvalid) ? g_x[g1] : 0.0f;
    __syncthreads();
    for (int size = 1024; size >= 1; size >>= 1) {
        float v = 0.0f;
        if (t < size) v = sh[2 * t] + sh[2 * t + 1];
        __syncthreads();
        if (t < size) sh[t] = v;
        __syncthreads();
    }
    if (t == 0) {
        g_L11[blockIdx.x] = sh[0];
        __threadfence();
        isLast = (atomicAdd(&g_tick, 1u) == NCHUNK - 1);
    }
    __syncthreads();
    if (!isLast) return;

    if (t == 0) g_tick = 0;   // reset for next graph replay
    float* Lv = sh;           // [0..510]
    float* Sv = sh + 512;     // [0..510]
    if (t < 256) Lv[t] = g_L11[t];
    __syncthreads();
    int off = 0, size = 256;
    for (int d = 0; d < 8; d++) {
        int noff = off + size, nsz = size >> 1;
        if (t < nsz) Lv[noff + t] = Lv[off + 2 * t] + Lv[off + 2 * t + 1];
        __syncthreads();
        off = noff; size = nsz;
    }
    if (t == 0) Sv[510] = Lv[510];
    __syncthreads();
    for (int d = 0; d < 8; d++) {
        int sz = 2 << d;
        off -= sz;
        int poff = off + sz;
        if (t < sz) {
            float v;
            if (t == 0)      v = Lv[off];
            else if (t & 1)  v = Sv[poff + ((t - 1) >> 1)];
            else             v = Sv[poff + (t >> 1) - 1] + Lv[off + t];
            Sv[off + t] = v;
        }
        __syncthreads();
    }
    if (t < 256) g_S11[t] = Sv[t];
}

// ---------------- scan C: up-sweep, writes S (level 0) --------------------
__global__ void scan_up_kernel()
{
    __shared__ float Lb[4094];
    __shared__ float Sa[2048];
    __shared__ float Sb[1024];
    int t = threadIdx.x;               // 1024
    int b = blockIdx.x;
    int base = b * 2048;
    u32 nvalid = g_cntbuf[HW];
    if (nvalid > NPAD) nvalid = NPAD;
    int g0 = base + t, g1 = base + t + 1024;
    Lb[t]        = ((u32)g0 < nvalid) ? g_x[g0] : 0.0f;
    Lb[t + 1024] = ((u32)g1 < nvalid) ? g_x[g1] : 0.0f;
    __syncthreads();
    int off = 0, size = 2048;
    for (int d = 1; d <= 10; d++) {
        int noff = off + size, nsz = size >> 1;
        for (int j = t; j < nsz; j += 1024)
            Lb[noff + j] = Lb[off + 2 * j] + Lb[off + 2 * j + 1];
        __syncthreads();
        off = noff; size = nsz;
    }
    float bound = (b > 0) ? g_S11[b - 1] : 0.0f;
    if (t == 0) {
        Sa[0] = (b == 0) ? Lb[off] : bound + Lb[off];
        Sa[1] = g_S11[b];
    }
    __syncthreads();
    for (int d = 9; d >= 0; d--) {
        int sz = 2048 >> d;
        off -= sz;
        float* Sprev = (d & 1) ? Sa : Sb;
        float* Scur  = (d & 1) ? Sb : Sa;
        for (int j = t; j < sz; j += 1024) {
            float v;
            if (j == 0)      v = (b == 0) ? Lb[off] : bound + Lb[off];
            else if (j & 1)  v = Sprev[(j - 1) >> 1];
            else             v = Sprev[(j >> 1) - 1] + Lb[off + j];
            Scur[j] = v;
        }
        __syncthreads();
    }
    g_S[base + t] = Sa[t];
    g_S[base + t + 1024] = Sa[t + 1024];
}

// ---------------- render ----------------
__global__ void render_kernel(const float* __restrict__ opac,
                              const float* __restrict__ feats,
                              float* __restrict__ out)
{
    int p = blockIdx.x * blockDim.x + threadIdx.x;
    if (p >= HW) return;
    u32 s = g_off[p];
    u32 k = g_cntbuf[p];

    float img0 = 0.0f, img1 = 0.0f, img2 = 0.0f;
    float dep = 0.0f;
    float Lsum = 0.0f;

    float c_end = (k > 0) ? g_S[s + k - 1] : 0.0f;
    for (u32 i = 0; i < k; i++) {
        u64 key = g_key[s + i];
        u32 idx = (u32)key;
        float z = key_z(key);
        float w = opac[idx];
        float T = expf(c_end - g_S[s + i]);
        float contrib = w * T;
        img0 += contrib * feats[3 * idx + 0];
        img1 += contrib * feats[3 * idx + 1];
        img2 += contrib * feats[3 * idx + 2];
        dep  += contrib * z;
        Lsum += g_x[s + i];
    }

    out[0 * HW + p] = img0;
    out[1 * HW + p] = img1;
    out[2 * HW + p] = img2;
    out[3 * HW + p] = dep;
    out[4 * HW + p] = 1.0f - expf(Lsum);
}

// ---------------- launch ----------------
extern "C" void kernel_launch(void* const* d_in, const int* in_sizes, int n_in,
                              void* d_out, int out_size)
{
    const float* means = (const float*)d_in[0];
    const float* opac  = (const float*)d_in[1];
    const float* feats = (const float*)d_in[2];
    const float* pose  = (const float*)d_in[3];
    float* out = (float*)d_out;

    int n = in_sizes[0] / 3;

    void* cnt_addr = nullptr; cudaGetSymbolAddress(&cnt_addr, g_cntbuf);
    cudaMemsetAsync(cnt_addr, 0, CNT_WORDS * sizeof(u32), 0);

    int npt = (n + PPT - 1) / PPT;
    project_count_kernel<<<(npt + PRJ_TPB - 1) / PRJ_TPB, PRJ_TPB>>>(
        (const float4*)means, means, opac, pose, n);
    scan_offsets_kernel<<<NSCAN_BLOCKS, SCAN_BLK>>>();
    place_kernel<<<NPAD / (256 * 2), 256>>>();
    sortemit_kernel<<<(HW + 255) / 256, 256>>>(opac);
    scan_down_kernel<<<NCHUNK, 1024>>>();
    scan_up_kernel<<<NCHUNK, 1024>>>();
    render_kernel<<<(HW + 255) / 256, 256>>>(opac, feats, out);
}

// round 11
// speedup vs baseline: 1.4217x; 1.0376x over previous
#include <cuda_runtime.h>
#include <cuda_bf16.h>
#include <math.h>

#define IMG_H 512
#define IMG_W 640
#define HW (IMG_H * IMG_W)            // 327680
#define FXc 500.0f
#define FYc 500.0f
#define CXc 320.0f
#define CYc 256.0f

#define SCAN_BLK 1024
#define NSCAN_BLOCKS 320              // HW / 1024
#define NPAD 524288                   // 2^19 >= n_valid (~345k)
#define NCHUNK 256                    // NPAD / 2048

#define PRJ_TPB 256
#define PRJ_WARPS (PRJ_TPB / 32)
#define PPT 4

typedef unsigned long long u64;
typedef unsigned int u32;

// ---------------- device scratch ----------------
// g_cntbuf layout: [0..HW) per-pixel counts | [HW] nvalid | [HW+1] pad |
//                  [HW+2 .. HW+2+2*NSCAN_BLOCKS) lookback descriptors (u64)
#define CNT_WORDS (HW + 2 + 2 * NSCAN_BLOCKS)
__device__ u32 g_cntbuf[CNT_WORDS];
__device__ u32 g_off[HW];
__device__ u32 g_woff[HW];
__device__ u32 g_tick;             // scan_down last-block ticket (self-reset)

__device__ u32 g_rpid[NPAD];       // unordered: pixel id per record
__device__ u64 g_rkey[NPAD];       // unordered: packed (z desc, idx) key
__device__ u64 g_key[NPAD];        // binned (then sorted in place)

__device__ float g_x[NPAD];        // lg at sorted positions
__device__ float g_S[NPAD];        // inclusive scan, assoc-scan rounding replicated
__device__ float g_L11[NCHUNK];
__device__ float g_S11[NCHUNK];

// key: ascending u64 sort == (z desc, idx asc). z>0 so float bits monotonic.
__device__ __forceinline__ u64 pack_key(float z, u32 idx)
{
    return ((u64)(0xFFFFFFFFu - __float_as_uint(z)) << 32) | (u64)idx;
}
__device__ __forceinline__ float key_z(u64 k)
{
    return __uint_as_float(0xFFFFFFFFu - (u32)(k >> 32));
}

// ---------------- pass 1: project 4 pts/thread (R1-verified rounding) -----
__global__ void project_count_kernel(const float4* __restrict__ means4,
                                     const float* __restrict__ means,
                                     const float* __restrict__ opac,
                                     const float* __restrict__ pose, int n)
{
    __shared__ u32 wcnt[PRJ_WARPS];
    __shared__ u32 woffs[PRJ_WARPS];
    __shared__ u32 sbase;

    int tbase = (blockIdx.x * blockDim.x + threadIdx.x) * PPT;
    int lane = threadIdx.x & 31;
    int warp = threadIdx.x >> 5;

    float m[PPT][3];
    bool valid[PPT];
    int pid[PPT];
    float zv[PPT];
    u32 cnt = 0;

#pragma unroll
    for (int q = 0; q < PPT; q++) { m[q][0] = 0.0f; m[q][1] = 0.0f; m[q][2] = -1.0f; }
    if (tbase + PPT <= n) {
        int v = tbase >> 2;
        float4 a = means4[3 * v + 0];
        float4 b = means4[3 * v + 1];
        float4 c = means4[3 * v + 2];
        m[0][0] = a.x; m[0][1] = a.y; m[0][2] = a.z;
        m[1][0] = a.w; m[1][1] = b.x; m[1][2] = b.y;
        m[2][0] = b.z; m[2][1] = b.w; m[2][2] = c.x;
        m[3][0] = c.y; m[3][1] = c.z; m[3][2] = c.w;
    } else if (tbase < n) {
        for (int q = 0; q < PPT; q++)
            if (tbase + q < n) {
                m[q][0] = means[3 * (tbase + q) + 0];
                m[q][1] = means[3 * (tbase + q) + 1];
                m[q][2] = means[3 * (tbase + q) + 2];
            }
    }

#pragma unroll
    for (int q = 0; q < PPT; q++) {
        float m0 = m[q][0], m1 = m[q][1], m2 = m[q][2];
        // pose is identity: exact regardless of order
        float pc0 = m0 * pose[0] + m1 * pose[1] + m2 * pose[2]  + pose[3];
        float pc1 = m0 * pose[4] + m1 * pose[5] + m2 * pose[6]  + pose[7];
        float z   = m0 * pose[8] + m1 * pose[9] + m2 * pose[10] + pose[11];
        // IEEE rn div/mul/add, NO fma (matches reference; measured best)
        float x = __fadd_rn(__fmul_rn(__fdiv_rn(pc0, z), FXc), CXc);
        float y = __fadd_rn(__fmul_rn(__fdiv_rn(pc1, z), FYc), CYc);
        bool ok = (tbase + q < n) && (x >= 0.0f) && (x < (float)IMG_W) &&
                  (y >= 0.0f) && (y < (float)IMG_H) && (z > 0.0f);
        valid[q] = ok;
        if (ok) {
            pid[q] = (int)floorf(y) * IMG_W + (int)floorf(x);
            zv[q] = z;
            cnt++;
        }
    }

    u32 pre = cnt;
#pragma unroll
    for (int d = 1; d < 32; d <<= 1) {
        u32 u = __shfl_up_sync(0xffffffffu, pre, d);
        if (lane >= d) pre += u;
    }
    if (lane == 31) wcnt[warp] = pre;
    __syncthreads();
    if (threadIdx.x == 0) {
        u32 run = 0;
#pragma unroll
        for (int wi = 0; wi < PRJ_WARPS; wi++) { woffs[wi] = run; run += wcnt[wi]; }
        sbase = (run > 0) ? atomicAdd(&g_cntbuf[HW], run) : 0u;
    }
    __syncthreads();

    u32 pos = sbase + woffs[warp] + (pre - cnt);
#pragma unroll
    for (int q = 0; q < PPT; q++) {
        if (valid[q]) {
            atomicAdd(&g_cntbuf[pid[q]], 1u);
            if (pos < NPAD) {
                g_rpid[pos] = (u32)pid[q];
                g_rkey[pos] = pack_key(zv[q], (u32)(tbase + q));
            }
            pos++;
        }
    }
}

// ---------------- offset scan: single pass, decoupled lookback ------------
__global__ void __launch_bounds__(SCAN_BLK)
scan_offsets_kernel()
{
    __shared__ u32 sh[SCAN_BLK];
    __shared__ u32 sprefix;
    u64* desc = (u64*)&g_cntbuf[HW + 2];

    int t = threadIdx.x;
    int b = blockIdx.x;
    int gi = b * SCAN_BLK + t;
    u32 v = g_cntbuf[gi];
    sh[t] = v;
    __syncthreads();
#pragma unroll
    for (int d = 1; d < SCAN_BLK; d <<= 1) {
        u32 add = (t >= d) ? sh[t - d] : 0u;
        __syncthreads();
        sh[t] += add;
        __syncthreads();
    }
    u32 agg = sh[SCAN_BLK - 1];

    if (t == 0) {
        u64 pub = (b == 0) ? ((2ull << 32) | (u64)agg)
                           : ((1ull << 32) | (u64)agg);
        atomicExch((unsigned long long*)&desc[b], pub);
        if (b == 0) sprefix = 0u;
    }

    if (b > 0 && t < 32) {
        u32 running = 0;
        int offset = b;
        while (true) {
            int j = offset - 1 - t;
            u64 d;
            if (j >= 0) {
                do {
                    d = atomicAdd((unsigned long long*)&desc[j], 0ull);
                } while ((u32)(d >> 32) == 0u);
            } else {
                d = (2ull << 32);
            }
            u32 status = (u32)(d >> 32);
            u32 val = (u32)d;
            u32 ballot = __ballot_sync(0xffffffffu, status == 2u);
            if (ballot) {
                int l2 = __ffs(ballot) - 1;
                u32 contrib = (t <= l2) ? val : 0u;
#pragma unroll
                for (int o = 16; o > 0; o >>= 1)
                    contrib += __shfl_down_sync(0xffffffffu, contrib, o);
                if (t == 0) running += contrib;
                break;
            } else {
                u32 contrib = val;
#pragma unroll
                for (int o = 16; o > 0; o >>= 1)
                    contrib += __shfl_down_sync(0xffffffffu, contrib, o);
                if (t == 0) running += contrib;
                offset -= 32;
            }
        }
        if (t == 0) {
            sprefix = running;
            atomicExch((unsigned long long*)&desc[b],
                       (2ull << 32) | (u64)(running + agg));
        }
    }
    __syncthreads();

    u32 o = sh[t] - v + sprefix;
    g_off[gi] = o;
    g_woff[gi] = o;
}

// ---------------- pass 2: place keys, 2 records/thread (MLP) --------------
__global__ void place_kernel()
{
    u32 nvalid = g_cntbuf[HW];
    if (nvalid > NPAD) nvalid = NPAD;
    u32 r0 = (blockIdx.x * blockDim.x + threadIdx.x) * 2;
    if (r0 >= nvalid) return;
    bool h1 = (r0 + 1 < nvalid);
    u32 pid0 = g_rpid[r0];
    u32 pid1 = h1 ? g_rpid[r0 + 1] : 0u;
    u64 key0 = g_rkey[r0];
    u64 key1 = h1 ? g_rkey[r0 + 1] : 0ull;
    u32 pos0 = atomicAdd(&g_woff[pid0], 1u);
    u32 pos1 = h1 ? atomicAdd(&g_woff[pid1], 1u) : 0u;
    if (pos0 < NPAD) g_key[pos0] = key0;
    if (h1 && pos1 < NPAD) g_key[pos1] = key1;
}

// ---------------- per-pixel sort via register sorting networks ------------
// Register paths only up to k=8 (keeps regs low -> occupancy).
// k>8 (P ~ 6e-4 of pixels) -> global-memory selection sort.
#define CSW(a, b) { u64 _lo = (a) < (b) ? (a) : (b); \
                    u64 _hi = (a) < (b) ? (b) : (a); (a) = _lo; (b) = _hi; }

__global__ void __launch_bounds__(256, 8)
sortemit_kernel(const float* __restrict__ opac)
{
    int p = blockIdx.x * blockDim.x + threadIdx.x;
    if (p >= HW) return;
    u32 s = g_off[p];
    u32 k = g_cntbuf[p];
    if (k == 0) return;

    if (k == 1) {
        u64 key = g_key[s];
        g_x[s] = log1pf(-opac[(u32)key]);
        return;
    }
    if (k <= 4) {
        u64 a[4];
#pragma unroll
        for (int i = 0; i < 4; i++)
            a[i] = ((u32)i < k) ? g_key[s + i] : ~0ull;
        CSW(a[0], a[1]); CSW(a[2], a[3]);
        CSW(a[0], a[2]); CSW(a[1], a[3]);
        CSW(a[1], a[2]);
#pragma unroll
        for (int i = 0; i < 4; i++)
            if ((u32)i < k) {
                g_key[s + i] = a[i];
                g_x[s + i] = log1pf(-opac[(u32)a[i]]);
            }
        return;
    }
    if (k <= 8) {
        u64 a[8];
#pragma unroll
        for (int i = 0; i < 8; i++)
            a[i] = ((u32)i < k) ? g_key[s + i] : ~0ull;
        // Batcher odd-even merge sort, 8 inputs, 19 CEs
        CSW(a[0], a[1]); CSW(a[2], a[3]); CSW(a[4], a[5]); CSW(a[6], a[7]);
        CSW(a[0], a[2]); CSW(a[1], a[3]); CSW(a[4], a[6]); CSW(a[5], a[7]);
        CSW(a[1], a[2]); CSW(a[5], a[6]);
        CSW(a[0], a[4]); CSW(a[1], a[5]); CSW(a[2], a[6]); CSW(a[3], a[7]);
        CSW(a[2], a[4]); CSW(a[3], a[5]);
        CSW(a[1], a[2]); CSW(a[3], a[4]); CSW(a[5], a[6]);
#pragma unroll
        for (int i = 0; i < 8; i++)
            if ((u32)i < k) {
                g_key[s + i] = a[i];
                g_x[s + i] = log1pf(-opac[(u32)a[i]]);
            }
        return;
    }
    // rare (P ~ 6e-4): global-memory selection sort, same comparator
    for (u32 i = 0; i < k; i++) {
        u32 best = i;
        u64 bv = g_key[s + i];
        for (u32 j = i + 1; j < k; j++) {
            u64 cv = g_key[s + j];
            if (cv < bv) { best = j; bv = cv; }
        }
        if (best != i) {
            u64 tmp = g_key[s + i];
            g_key[s + i] = bv;
            g_key[s + best] = tmp;
        }
        g_x[s + i] = log1pf(-opac[(u32)bv]);
    }
}

// ---------------- scan A: per-chunk tree sum + fused mid scan -------------
__global__ void scan_down_kernel()
{
    __shared__ float sh[2048];
    __shared__ bool isLast;
    int t = threadIdx.x;               // 1024
    int base = blockIdx.x * 2048;
    u32 nvalid = g_cntbuf[HW];
    if (nvalid > NPAD) nvalid = NPAD;
    int g0 = base + t, g1 = base + t + 1024;
    sh[t]        = ((u32)g0 < nvalid) ? g_x[g0] : 0.0f;
    sh[t + 1024] = ((u32)g1 < nvalid) ? g_x[g1] : 0.0f;
    __syncthreads();
    for (int size = 1024; size >= 1; size >>= 1) {
        float v = 0.0f;
        if (t < size) v = sh[2 * t] + sh[2 * t + 1];
        __syncthreads();
        if (t < size) sh[t] = v;
        __syncthreads();
    }
    if (t == 0) {
        g_L11[blockIdx.x] = sh[0];
        __threadfence();
        isLast = (atomicAdd(&g_tick, 1u) == NCHUNK - 1);
    }
    __syncthreads();
    if (!isLast) return;

    if (t == 0) g_tick = 0;   // reset for next graph replay
    float* Lv = sh;           // [0..510]
    float* Sv = sh + 512;     // [0..510]
    if (t < 256) Lv[t] = g_L11[t];
    __syncthreads();
    int off = 0, size = 256;
    for (int d = 0; d < 8; d++) {
        int noff = off + size, nsz = size >> 1;
        if (t < nsz) Lv[noff + t] = Lv[off + 2 * t] + Lv[off + 2 * t + 1];
        __syncthreads();
        off = noff; size = nsz;
    }
    if (t == 0) Sv[510] = Lv[510];
    __syncthreads();
    for (int d = 0; d < 8; d++) {
        int sz = 2 << d;
        off -= sz;
        int poff = off + sz;
        if (t < sz) {
            float v;
            if (t == 0)      v = Lv[off];
            else if (t & 1)  v = Sv[poff + ((t - 1) >> 1)];
            else             v = Sv[poff + (t >> 1) - 1] + Lv[off + t];
            Sv[off + t] = v;
        }
        __syncthreads();
    }
    if (t < 256) g_S11[t] = Sv[t];
}

// ---------------- scan C: up-sweep, writes S (level 0) --------------------
__global__ void scan_up_kernel()
{
    __shared__ float Lb[4094];
    __shared__ float Sa[2048];
    __shared__ float Sb[1024];
    int t = threadIdx.x;               // 1024
    int b = blockIdx.x;
    int base = b * 2048;
    u32 nvalid = g_cntbuf[HW];
    if (nvalid > NPAD) nvalid = NPAD;
    int g0 = base + t, g1 = base + t + 1024;
    Lb[t]        = ((u32)g0 < nvalid) ? g_x[g0] : 0.0f;
    Lb[t + 1024] = ((u32)g1 < nvalid) ? g_x[g1] : 0.0f;
    __syncthreads();
    int off = 0, size = 2048;
    for (int d = 1; d <= 10; d++) {
        int noff = off + size, nsz = size >> 1;
        for (int j = t; j < nsz; j += 1024)
            Lb[noff + j] = Lb[off + 2 * j] + Lb[off + 2 * j + 1];
        __syncthreads();
        off = noff; size = nsz;
    }
    float bound = (b > 0) ? g_S11[b - 1] : 0.0f;
    if (t == 0) {
        Sa[0] = (b == 0) ? Lb[off] : bound + Lb[off];
        Sa[1] = g_S11[b];
    }
    __syncthreads();
    for (int d = 9; d >= 0; d--) {
        int sz = 2048 >> d;
        off -= sz;
        float* Sprev = (d & 1) ? Sa : Sb;
        float* Scur  = (d & 1) ? Sb : Sa;
        for (int j = t; j < sz; j += 1024) {
            float v;
            if (j == 0)      v = (b == 0) ? Lb[off] : bound + Lb[off];
            else if (j & 1)  v = Sprev[(j - 1) >> 1];
            else             v = Sprev[(j >> 1) - 1] + Lb[off + j];
            Scur[j] = v;
        }
        __syncthreads();
    }
    g_S[base + t] = Sa[t];
    g_S[base + t + 1024] = Sa[t + 1024];
}

// ---------------- render ----------------
__global__ void render_kernel(const float* __restrict__ opac,
                              const float* __restrict__ feats,
                              float* __restrict__ out)
{
    int p = blockIdx.x * blockDim.x + threadIdx.x;
    if (p >= HW) return;
    u32 s = g_off[p];
    u32 k = g_cntbuf[p];

    float img0 = 0.0f, img1 = 0.0f, img2 = 0.0f;
    float dep = 0.0f;
    float Lsum = 0.0f;

    float c_end = (k > 0) ? g_S[s + k - 1] : 0.0f;
    for (u32 i = 0; i < k; i++) {
        u64 key = g_key[s + i];
        u32 idx = (u32)key;
        float z = key_z(key);
        float w = opac[idx];
        float T = expf(c_end - g_S[s + i]);
        float contrib = w * T;
        img0 += contrib * feats[3 * idx + 0];
        img1 += contrib * feats[3 * idx + 1];
        img2 += contrib * feats[3 * idx + 2];
        dep  += contrib * z;
        Lsum += g_x[s + i];
    }

    out[0 * HW + p] = img0;
    out[1 * HW + p] = img1;
    out[2 * HW + p] = img2;
    out[3 * HW + p] = dep;
    out[4 * HW + p] = 1.0f - expf(Lsum);
}

// ---------------- launch ----------------
extern "C" void kernel_launch(void* const* d_in, const int* in_sizes, int n_in,
                              void* d_out, int out_size)
{
    const float* means = (const float*)d_in[0];
    const float* opac  = (const float*)d_in[1];
    const float* feats = (const float*)d_in[2];
    const float* pose  = (const float*)d_in[3];
    float* out = (float*)d_out;

    int n = in_sizes[0] / 3;

    void* cnt_addr = nullptr; cudaGetSymbolAddress(&cnt_addr, g_cntbuf);
    cudaMemsetAsync(cnt_addr, 0, CNT_WORDS * sizeof(u32), 0);

    int npt = (n + PPT - 1) / PPT;
    project_count_kernel<<<(npt + PRJ_TPB - 1) / PRJ_TPB, PRJ_TPB>>>(
        (const float4*)means, means, opac, pose, n);
    scan_offsets_kernel<<<NSCAN_BLOCKS, SCAN_BLK>>>();
    place_kernel<<<NPAD / (256 * 2), 256>>>();
    sortemit_kernel<<<(HW + 255) / 256, 256>>>(opac);
    scan_down_kernel<<<NCHUNK, 1024>>>();
    scan_up_kernel<<<NCHUNK, 1024>>>();
    render_kernel<<<(HW + 255) / 256, 256>>>(opac, feats, out);
}

// round 12
// speedup vs baseline: 1.9649x; 1.3821x over previous
#include <cuda_runtime.h>
#include <cuda_bf16.h>
#include <math.h>

#define IMG_H 512
#define IMG_W 640
#define HW (IMG_H * IMG_W)            // 327680
#define FXc 500.0f
#define FYc 500.0f
#define CXc 320.0f
#define CYc 256.0f

#define SCAN_BLK 1024
#define NSCAN_BLOCKS 320              // HW / 1024
#define NPAD 524288                   // 2^19 >= n_valid (~345k)

#define PRJ_TPB 256
#define PRJ_WARPS (PRJ_TPB / 32)
#define PPT 4

typedef unsigned long long u64;
typedef unsigned int u32;

// ---------------- device scratch ----------------
// g_cntbuf layout: [0..HW) per-pixel counts | [HW] nvalid | [HW+1] pad |
//                  [HW+2 .. HW+2+2*NSCAN_BLOCKS) lookback descriptors (u64)
#define CNT_WORDS (HW + 2 + 2 * NSCAN_BLOCKS)
__device__ u32 g_cntbuf[CNT_WORDS];
__device__ u32 g_off[HW];
__device__ u32 g_woff[HW];

__device__ u32 g_rpid[NPAD];       // unordered: pixel id per record
__device__ u64 g_rkey[NPAD];       // unordered: packed (z desc, idx) key
__device__ u64 g_key[NPAD];        // binned keys (sorted in fallback path only)

// key: ascending u64 sort == (z desc, idx asc). z>0 so float bits monotonic.
__device__ __forceinline__ u64 pack_key(float z, u32 idx)
{
    return ((u64)(0xFFFFFFFFu - __float_as_uint(z)) << 32) | (u64)idx;
}
__device__ __forceinline__ float key_z(u64 k)
{
    return __uint_as_float(0xFFFFFFFFu - (u32)(k >> 32));
}

// ---------------- pass 1: project 4 pts/thread (R1-verified rounding) -----
__global__ void project_count_kernel(const float4* __restrict__ means4,
                                     const float* __restrict__ means,
                                     const float* __restrict__ opac,
                                     const float* __restrict__ pose, int n)
{
    __shared__ u32 wcnt[PRJ_WARPS];
    __shared__ u32 woffs[PRJ_WARPS];
    __shared__ u32 sbase;

    int tbase = (blockIdx.x * blockDim.x + threadIdx.x) * PPT;
    int lane = threadIdx.x & 31;
    int warp = threadIdx.x >> 5;

    float m[PPT][3];
    bool valid[PPT];
    int pid[PPT];
    float zv[PPT];
    u32 cnt = 0;

#pragma unroll
    for (int q = 0; q < PPT; q++) { m[q][0] = 0.0f; m[q][1] = 0.0f; m[q][2] = -1.0f; }
    if (tbase + PPT <= n) {
        int v = tbase >> 2;
        float4 a = means4[3 * v + 0];
        float4 b = means4[3 * v + 1];
        float4 c = means4[3 * v + 2];
        m[0][0] = a.x; m[0][1] = a.y; m[0][2] = a.z;
        m[1][0] = a.w; m[1][1] = b.x; m[1][2] = b.y;
        m[2][0] = b.z; m[2][1] = b.w; m[2][2] = c.x;
        m[3][0] = c.y; m[3][1] = c.z; m[3][2] = c.w;
    } else if (tbase < n) {
        for (int q = 0; q < PPT; q++)
            if (tbase + q < n) {
                m[q][0] = means[3 * (tbase + q) + 0];
                m[q][1] = means[3 * (tbase + q) + 1];
                m[q][2] = means[3 * (tbase + q) + 2];
            }
    }

#pragma unroll
    for (int q = 0; q < PPT; q++) {
        float m0 = m[q][0], m1 = m[q][1], m2 = m[q][2];
        // pose is identity: exact regardless of order
        float pc0 = m0 * pose[0] + m1 * pose[1] + m2 * pose[2]  + pose[3];
        float pc1 = m0 * pose[4] + m1 * pose[5] + m2 * pose[6]  + pose[7];
        float z   = m0 * pose[8] + m1 * pose[9] + m2 * pose[10] + pose[11];
        // IEEE rn div/mul/add, NO fma (matches reference; measured best)
        float x = __fadd_rn(__fmul_rn(__fdiv_rn(pc0, z), FXc), CXc);
        float y = __fadd_rn(__fmul_rn(__fdiv_rn(pc1, z), FYc), CYc);
        bool ok = (tbase + q < n) && (x >= 0.0f) && (x < (float)IMG_W) &&
                  (y >= 0.0f) && (y < (float)IMG_H) && (z > 0.0f);
        valid[q] = ok;
        if (ok) {
            pid[q] = (int)floorf(y) * IMG_W + (int)floorf(x);
            zv[q] = z;
            cnt++;
        }
    }

    u32 pre = cnt;
#pragma unroll
    for (int d = 1; d < 32; d <<= 1) {
        u32 u = __shfl_up_sync(0xffffffffu, pre, d);
        if (lane >= d) pre += u;
    }
    if (lane == 31) wcnt[warp] = pre;
    __syncthreads();
    if (threadIdx.x == 0) {
        u32 run = 0;
#pragma unroll
        for (int wi = 0; wi < PRJ_WARPS; wi++) { woffs[wi] = run; run += wcnt[wi]; }
        sbase = (run > 0) ? atomicAdd(&g_cntbuf[HW], run) : 0u;
    }
    __syncthreads();

    u32 pos = sbase + woffs[warp] + (pre - cnt);
#pragma unroll
    for (int q = 0; q < PPT; q++) {
        if (valid[q]) {
            atomicAdd(&g_cntbuf[pid[q]], 1u);
            if (pos < NPAD) {
                g_rpid[pos] = (u32)pid[q];
                g_rkey[pos] = pack_key(zv[q], (u32)(tbase + q));
            }
            pos++;
        }
    }
}

// ---------------- offset scan: single pass, decoupled lookback ------------
__global__ void __launch_bounds__(SCAN_BLK)
scan_offsets_kernel()
{
    __shared__ u32 sh[SCAN_BLK];
    __shared__ u32 sprefix;
    u64* desc = (u64*)&g_cntbuf[HW + 2];

    int t = threadIdx.x;
    int b = blockIdx.x;
    int gi = b * SCAN_BLK + t;
    u32 v = g_cntbuf[gi];
    sh[t] = v;
    __syncthreads();
#pragma unroll
    for (int d = 1; d < SCAN_BLK; d <<= 1) {
        u32 add = (t >= d) ? sh[t - d] : 0u;
        __syncthreads();
        sh[t] += add;
        __syncthreads();
    }
    u32 agg = sh[SCAN_BLK - 1];

    if (t == 0) {
        u64 pub = (b == 0) ? ((2ull << 32) | (u64)agg)
                           : ((1ull << 32) | (u64)agg);
        atomicExch((unsigned long long*)&desc[b], pub);
        if (b == 0) sprefix = 0u;
    }

    if (b > 0 && t < 32) {
        u32 running = 0;
        int offset = b;
        while (true) {
            int j = offset - 1 - t;
            u64 d;
            if (j >= 0) {
                do {
                    d = atomicAdd((unsigned long long*)&desc[j], 0ull);
                } while ((u32)(d >> 32) == 0u);
            } else {
                d = (2ull << 32);
            }
            u32 status = (u32)(d >> 32);
            u32 val = (u32)d;
            u32 ballot = __ballot_sync(0xffffffffu, status == 2u);
            if (ballot) {
                int l2 = __ffs(ballot) - 1;
                u32 contrib = (t <= l2) ? val : 0u;
#pragma unroll
                for (int o = 16; o > 0; o >>= 1)
                    contrib += __shfl_down_sync(0xffffffffu, contrib, o);
                if (t == 0) running += contrib;
                break;
            } else {
                u32 contrib = val;
#pragma unroll
                for (int o = 16; o > 0; o >>= 1)
                    contrib += __shfl_down_sync(0xffffffffu, contrib, o);
                if (t == 0) running += contrib;
                offset -= 32;
            }
        }
        if (t == 0) {
            sprefix = running;
            atomicExch((unsigned long long*)&desc[b],
                       (2ull << 32) | (u64)(running + agg));
        }
    }
    __syncthreads();

    u32 o = sh[t] - v + sprefix;
    g_off[gi] = o;
    g_woff[gi] = o;
}

// ---------------- pass 2: place keys, 2 records/thread (MLP) --------------
__global__ void place_kernel()
{
    u32 nvalid = g_cntbuf[HW];
    if (nvalid > NPAD) nvalid = NPAD;
    u32 r0 = (blockIdx.x * blockDim.x + threadIdx.x) * 2;
    if (r0 >= nvalid) return;
    bool h1 = (r0 + 1 < nvalid);
    u32 pid0 = g_rpid[r0];
    u32 pid1 = h1 ? g_rpid[r0 + 1] : 0u;
    u64 key0 = g_rkey[r0];
    u64 key1 = h1 ? g_rkey[r0 + 1] : 0ull;
    u32 pos0 = atomicAdd(&g_woff[pid0], 1u);
    u32 pos1 = h1 ? atomicAdd(&g_woff[pid1], 1u) : 0u;
    if (pos0 < NPAD) g_key[pos0] = key0;
    if (h1 && pos1 < NPAD) g_key[pos1] = key1;
}

// ---------------- fused sort + exact compositing render -------------------
// Sorted order: ascending u64 key == (z desc, idx asc) == reference lexsort.
// Exact compositing: T_i = prod_{j>i}(1 - w_j); contrib_i = w_i * T_i.
// (R0/R2 measurements show this matches the reference as well as or better
//  than the replicated assoc-scan; binning arithmetic is untouched.)
#define CSW(a, b) { u64 _lo = (a) < (b) ? (a) : (b); \
                    u64 _hi = (a) < (b) ? (b) : (a); (a) = _lo; (b) = _hi; }

__global__ void __launch_bounds__(256, 6)
render_kernel(const float* __restrict__ opac,
              const float* __restrict__ feats,
              float* __restrict__ out)
{
    int p = blockIdx.x * blockDim.x + threadIdx.x;
    if (p >= HW) return;
    u32 s = g_off[p];
    u32 k = g_cntbuf[p];

    float img0 = 0.0f, img1 = 0.0f, img2 = 0.0f;
    float dep = 0.0f;
    float Lsum = 0.0f;

    if (k > 0 && k <= 8) {
        u64 a[8];
#pragma unroll
        for (int i = 0; i < 8; i++)
            a[i] = ((u32)i < k) ? g_key[s + i] : ~0ull;
        if (k > 1) {
            // Batcher odd-even merge sort, 8 inputs (pads sort to the end)
            CSW(a[0], a[1]); CSW(a[2], a[3]); CSW(a[4], a[5]); CSW(a[6], a[7]);
            CSW(a[0], a[2]); CSW(a[1], a[3]); CSW(a[4], a[6]); CSW(a[5], a[7]);
            CSW(a[1], a[2]); CSW(a[5], a[6]);
            CSW(a[0], a[4]); CSW(a[1], a[5]); CSW(a[2], a[6]); CSW(a[3], a[7]);
            CSW(a[2], a[4]); CSW(a[3], a[5]);
            CSW(a[1], a[2]); CSW(a[3], a[4]); CSW(a[5], a[6]);
        }
        float w[8];
#pragma unroll
        for (int i = 0; i < 8; i++)
            w[i] = ((u32)i < k) ? opac[(u32)a[i]] : 0.0f;

        float T = 1.0f;
#pragma unroll
        for (int i = 7; i >= 0; i--) {
            if ((u32)i < k) {
                float contrib = w[i] * T;
                u32 idx = (u32)a[i];
                img0 += contrib * feats[3 * idx + 0];
                img1 += contrib * feats[3 * idx + 1];
                img2 += contrib * feats[3 * idx + 2];
                dep  += contrib * key_z(a[i]);
                Lsum += log1pf(-w[i]);
                T *= (1.0f - w[i]);
            }
        }
    } else if (k > 8) {
        // rare fallback: selection sort in global memory, then composite
        for (u32 i = 0; i < k; i++) {
            u32 best = i;
            u64 bv = g_key[s + i];
            for (u32 j = i + 1; j < k; j++) {
                u64 cv = g_key[s + j];
                if (cv < bv) { best = j; bv = cv; }
            }
            if (best != i) {
                u64 tmp = g_key[s + i];
                g_key[s + i] = bv;
                g_key[s + best] = tmp;
            }
        }
        float T = 1.0f;
        for (int i = (int)k - 1; i >= 0; i--) {
            u64 key = g_key[s + i];
            u32 idx = (u32)key;
            float wv = opac[idx];
            float contrib = wv * T;
            img0 += contrib * feats[3 * idx + 0];
            img1 += contrib * feats[3 * idx + 1];
            img2 += contrib * feats[3 * idx + 2];
            dep  += contrib * key_z(key);
            Lsum += log1pf(-wv);
            T *= (1.0f - wv);
        }
    }

    out[0 * HW + p] = img0;
    out[1 * HW + p] = img1;
    out[2 * HW + p] = img2;
    out[3 * HW + p] = dep;
    out[4 * HW + p] = 1.0f - expf(Lsum);
}

// ---------------- launch ----------------
extern "C" void kernel_launch(void* const* d_in, const int* in_sizes, int n_in,
                              void* d_out, int out_size)
{
    const float* means = (const float*)d_in[0];
    const float* opac  = (const float*)d_in[1];
    const float* feats = (const float*)d_in[2];
    const float* pose  = (const float*)d_in[3];
    float* out = (float*)d_out;

    int n = in_sizes[0] / 3;

    void* cnt_addr = nullptr; cudaGetSymbolAddress(&cnt_addr, g_cntbuf);
    cudaMemsetAsync(cnt_addr, 0, CNT_WORDS * sizeof(u32), 0);

    int npt = (n + PPT - 1) / PPT;
    project_count_kernel<<<(npt + PRJ_TPB - 1) / PRJ_TPB, PRJ_TPB>>>(
        (const float4*)means, means, opac, pose, n);
    scan_offsets_kernel<<<NSCAN_BLOCKS, SCAN_BLK>>>();
    place_kernel<<<NPAD / (256 * 2), 256>>>();
    render_kernel<<<(HW + 255) / 256, 256>>>(opac, feats, out);
}

// round 13
// speedup vs baseline: 2.4828x; 1.2635x over previous
#include <cuda_runtime.h>
#include <cuda_bf16.h>
#include <math.h>

#define IMG_H 512
#define IMG_W 640
#define HW (IMG_H * IMG_W)            // 327680
#define FXc 500.0f
#define FYc 500.0f
#define CXc 320.0f
#define CYc 256.0f

#define PRJ_TPB 256
#define PPT 4
#define SLOTS 8
#define OVCAP 8192
#define LMAX 48                       // overflow-pixel local sort cap

typedef unsigned long long u64;
typedef unsigned int u32;

// ---------------- device scratch ----------------
// g_cnt: [0..HW) per-pixel counts | [HW] overflow count
__device__ u32 g_cnt[HW + 2];
__device__ u64 g_slot[(size_t)HW * SLOTS];   // 21MB, NOT zeroed (counts gate)
__device__ u64 g_ovk[OVCAP];
__device__ u32 g_ovp[OVCAP];

// key: ascending u64 sort == (z desc, idx asc). z>0 so float bits monotonic.
__device__ __forceinline__ u64 pack_key(float z, u32 idx)
{
    return ((u64)(0xFFFFFFFFu - __float_as_uint(z)) << 32) | (u64)idx;
}
__device__ __forceinline__ float key_z(u64 k)
{
    return __uint_as_float(0xFFFFFFFFu - (u32)(k >> 32));
}

// ---------------- pass 1: project 4 pts/thread + direct slot scatter ------
// Projection arithmetic bit-identical to R1 (measured best):
// separate __fmul_rn/__fadd_rn, NO fma contraction.
__global__ void project_scatter_kernel(const float4* __restrict__ means4,
                                       const float* __restrict__ means,
                                       const float* __restrict__ pose, int n)
{
    int tbase = (blockIdx.x * blockDim.x + threadIdx.x) * PPT;
    if (tbase >= n) return;

    float m[PPT][3];
#pragma unroll
    for (int q = 0; q < PPT; q++) { m[q][0] = 0.0f; m[q][1] = 0.0f; m[q][2] = -1.0f; }
    if (tbase + PPT <= n) {
        int v = tbase >> 2;
        float4 a = means4[3 * v + 0];
        float4 b = means4[3 * v + 1];
        float4 c = means4[3 * v + 2];
        m[0][0] = a.x; m[0][1] = a.y; m[0][2] = a.z;
        m[1][0] = a.w; m[1][1] = b.x; m[1][2] = b.y;
        m[2][0] = b.z; m[2][1] = b.w; m[2][2] = c.x;
        m[3][0] = c.y; m[3][1] = c.z; m[3][2] = c.w;
    } else {
        for (int q = 0; q < PPT; q++)
            if (tbase + q < n) {
                m[q][0] = means[3 * (tbase + q) + 0];
                m[q][1] = means[3 * (tbase + q) + 1];
                m[q][2] = means[3 * (tbase + q) + 2];
            }
    }

#pragma unroll
    for (int q = 0; q < PPT; q++) {
        float m0 = m[q][0], m1 = m[q][1], m2 = m[q][2];
        // pose is identity: exact regardless of order
        float pc0 = m0 * pose[0] + m1 * pose[1] + m2 * pose[2]  + pose[3];
        float pc1 = m0 * pose[4] + m1 * pose[5] + m2 * pose[6]  + pose[7];
        float z   = m0 * pose[8] + m1 * pose[9] + m2 * pose[10] + pose[11];
        // IEEE rn div/mul/add, NO fma (matches reference; measured best)
        float x = __fadd_rn(__fmul_rn(__fdiv_rn(pc0, z), FXc), CXc);
        float y = __fadd_rn(__fmul_rn(__fdiv_rn(pc1, z), FYc), CYc);
        bool ok = (tbase + q < n) && (x >= 0.0f) && (x < (float)IMG_W) &&
                  (y >= 0.0f) && (y < (float)IMG_H) && (z > 0.0f);
        if (ok) {
            u32 pid = (u32)((int)floorf(y) * IMG_W + (int)floorf(x));
            u64 key = pack_key(z, (u32)(tbase + q));
            u32 pos = atomicAdd(&g_cnt[pid], 1u);
            if (pos < SLOTS) {
                g_slot[(size_t)pid * SLOTS + pos] = key;
            } else {
                u32 o = atomicAdd(&g_cnt[HW], 1u);
                if (o < OVCAP) { g_ovk[o] = key; g_ovp[o] = pid; }
            }
        }
    }
}

// ---------------- fused sort + exact compositing render -------------------
// Sorted order: ascending u64 key == (z desc, idx asc) == reference lexsort.
// Exact compositing: T_i = prod_{j>i}(1 - w_j); contrib_i = w_i * T_i.
#define CSW(a, b) { u64 _lo = (a) < (b) ? (a) : (b); \
                    u64 _hi = (a) < (b) ? (b) : (a); (a) = _lo; (b) = _hi; }

__global__ void __launch_bounds__(256, 6)
render_kernel(const float* __restrict__ opac,
              const float* __restrict__ feats,
              float* __restrict__ out)
{
    int p = blockIdx.x * blockDim.x + threadIdx.x;
    if (p >= HW) return;
    u32 k = g_cnt[p];
    const u64* slot = &g_slot[(size_t)p * SLOTS];

    float img0 = 0.0f, img1 = 0.0f, img2 = 0.0f;
    float dep = 0.0f;
    float Lsum = 0.0f;

    if (k == 1) {
        u64 key = slot[0];
        u32 idx = (u32)key;
        float wv = opac[idx];
        img0 = wv * feats[3 * idx + 0];
        img1 = wv * feats[3 * idx + 1];
        img2 = wv * feats[3 * idx + 2];
        dep  = wv * key_z(key);
        Lsum = log1pf(-wv);
    } else if (k > 1 && k <= 4) {
        u64 a[4];
#pragma unroll
        for (int i = 0; i < 4; i++)
            a[i] = ((u32)i < k) ? slot[i] : ~0ull;
        CSW(a[0], a[1]); CSW(a[2], a[3]);
        CSW(a[0], a[2]); CSW(a[1], a[3]);
        CSW(a[1], a[2]);
        float w[4];
#pragma unroll
        for (int i = 0; i < 4; i++)
            w[i] = ((u32)i < k) ? opac[(u32)a[i]] : 0.0f;
        float T = 1.0f;
#pragma unroll
        for (int i = 3; i >= 0; i--) {
            if ((u32)i < k) {
                float contrib = w[i] * T;
                u32 idx = (u32)a[i];
                img0 += contrib * feats[3 * idx + 0];
                img1 += contrib * feats[3 * idx + 1];
                img2 += contrib * feats[3 * idx + 2];
                dep  += contrib * key_z(a[i]);
                Lsum += log1pf(-w[i]);
                T *= (1.0f - w[i]);
            }
        }
    } else if (k > 4 && k <= 8) {
        u64 a[8];
#pragma unroll
        for (int i = 0; i < 8; i++)
            a[i] = ((u32)i < k) ? slot[i] : ~0ull;
        // Batcher odd-even merge sort, 8 inputs, 19 CEs
        CSW(a[0], a[1]); CSW(a[2], a[3]); CSW(a[4], a[5]); CSW(a[6], a[7]);
        CSW(a[0], a[2]); CSW(a[1], a[3]); CSW(a[4], a[6]); CSW(a[5], a[7]);
        CSW(a[1], a[2]); CSW(a[5], a[6]);
        CSW(a[0], a[4]); CSW(a[1], a[5]); CSW(a[2], a[6]); CSW(a[3], a[7]);
        CSW(a[2], a[4]); CSW(a[3], a[5]);
        CSW(a[1], a[2]); CSW(a[3], a[4]); CSW(a[5], a[6]);
        float w[8];
#pragma unroll
        for (int i = 0; i < 8; i++)
            w[i] = ((u32)i < k) ? opac[(u32)a[i]] : 0.0f;
        float T = 1.0f;
#pragma unroll
        for (int i = 7; i >= 0; i--) {
            if ((u32)i < k) {
                float contrib = w[i] * T;
                u32 idx = (u32)a[i];
                img0 += contrib * feats[3 * idx + 0];
                img1 += contrib * feats[3 * idx + 1];
                img2 += contrib * feats[3 * idx + 2];
                dep  += contrib * key_z(a[i]);
                Lsum += log1pf(-w[i]);
                T *= (1.0f - w[i]);
            }
        }
    } else if (k > 8) {
        // overflow pixel (expected ~0-2 per frame): merge slots + overflow
        u64 list[LMAX];
        int mcount = 0;
        for (int i = 0; i < SLOTS; i++) list[mcount++] = slot[i];
        u32 ovn = g_cnt[HW];
        if (ovn > OVCAP) ovn = OVCAP;
        for (u32 j = 0; j < ovn; j++)
            if (g_ovp[j] == (u32)p && mcount < LMAX) list[mcount++] = g_ovk[j];
        // insertion sort ascending
        for (int i = 1; i < mcount; i++) {
            u64 key = list[i];
            int j = i - 1;
            while (j >= 0 && list[j] > key) { list[j + 1] = list[j]; j--; }
            list[j + 1] = key;
        }
        float T = 1.0f;
        for (int i = mcount - 1; i >= 0; i--) {
            u64 key = list[i];
            u32 idx = (u32)key;
            float wv = opac[idx];
            float contrib = wv * T;
            img0 += contrib * feats[3 * idx + 0];
            img1 += contrib * feats[3 * idx + 1];
            img2 += contrib * feats[3 * idx + 2];
            dep  += contrib * key_z(key);
            Lsum += log1pf(-wv);
            T *= (1.0f - wv);
        }
    }

    out[0 * HW + p] = img0;
    out[1 * HW + p] = img1;
    out[2 * HW + p] = img2;
    out[3 * HW + p] = dep;
    out[4 * HW + p] = 1.0f - expf(Lsum);
}

// ---------------- launch: 3 graph nodes ----------------
extern "C" void kernel_launch(void* const* d_in, const int* in_sizes, int n_in,
                              void* d_out, int out_size)
{
    const float* means = (const float*)d_in[0];
    const float* opac  = (const float*)d_in[1];
    const float* feats = (const float*)d_in[2];
    const float* pose  = (const float*)d_in[3];
    float* out = (float*)d_out;

    int n = in_sizes[0] / 3;

    void* cnt_addr = nullptr; cudaGetSymbolAddress(&cnt_addr, g_cnt);
    cudaMemsetAsync(cnt_addr, 0, (HW + 2) * sizeof(u32), 0);

    int npt = (n + PPT - 1) / PPT;
    project_scatter_kernel<<<(npt + PRJ_TPB - 1) / PRJ_TPB, PRJ_TPB>>>(
        (const float4*)means, means, pose, n);
    render_kernel<<<(HW + 255) / 256, 256>>>(opac, feats, out);
}

// round 14
// speedup vs baseline: 2.5736x; 1.0366x over previous
#include <cuda_runtime.h>
#include <cuda_bf16.h>
#include <math.h>

#define IMG_H 512
#define IMG_W 640
#define HW (IMG_H * IMG_W)            // 327680
#define FXc 500.0f
#define FYc 500.0f
#define CXc 320.0f
#define CYc 256.0f

#define PRJ_TPB 256
#define PPT 4
#define SLOTS 8
#define OVCAP 8192
#define LMAX 48                       // overflow-pixel local sort cap

typedef unsigned long long u64;
typedef unsigned int u32;

// ---------------- device scratch ----------------
// g_cnt: [0..HW) per-pixel counts | [HW] overflow count
__device__ u32 g_cnt[HW + 2];
// SoA: slot n for pixel p at g_slot[n*HW + p]  (coalesced render reads)
__device__ u64 g_slot[(size_t)SLOTS * HW];   // 21MB, NOT zeroed (counts gate)
__device__ u64 g_ovk[OVCAP];
__device__ u32 g_ovp[OVCAP];

// key: ascending u64 sort == (z desc, idx asc). z>0 so float bits monotonic.
__device__ __forceinline__ u64 pack_key(float z, u32 idx)
{
    return ((u64)(0xFFFFFFFFu - __float_as_uint(z)) << 32) | (u64)idx;
}
__device__ __forceinline__ float key_z(u64 k)
{
    return __uint_as_float(0xFFFFFFFFu - (u32)(k >> 32));
}

// ---------------- pass 1: project 4 pts/thread + direct slot scatter ------
// Projection arithmetic bit-identical to R1 (measured best):
// separate __fmul_rn/__fadd_rn, NO fma contraction.
__global__ void project_scatter_kernel(const float4* __restrict__ means4,
                                       const float* __restrict__ means,
                                       const float* __restrict__ pose, int n)
{
    int tbase = (blockIdx.x * blockDim.x + threadIdx.x) * PPT;
    if (tbase >= n) return;

    float m[PPT][3];
#pragma unroll
    for (int q = 0; q < PPT; q++) { m[q][0] = 0.0f; m[q][1] = 0.0f; m[q][2] = -1.0f; }
    if (tbase + PPT <= n) {
        int v = tbase >> 2;
        float4 a = means4[3 * v + 0];
        float4 b = means4[3 * v + 1];
        float4 c = means4[3 * v + 2];
        m[0][0] = a.x; m[0][1] = a.y; m[0][2] = a.z;
        m[1][0] = a.w; m[1][1] = b.x; m[1][2] = b.y;
        m[2][0] = b.z; m[2][1] = b.w; m[2][2] = c.x;
        m[3][0] = c.y; m[3][1] = c.z; m[3][2] = c.w;
    } else {
        for (int q = 0; q < PPT; q++)
            if (tbase + q < n) {
                m[q][0] = means[3 * (tbase + q) + 0];
                m[q][1] = means[3 * (tbase + q) + 1];
                m[q][2] = means[3 * (tbase + q) + 2];
            }
    }

#pragma unroll
    for (int q = 0; q < PPT; q++) {
        float m0 = m[q][0], m1 = m[q][1], m2 = m[q][2];
        // pose is identity: exact regardless of order
        float pc0 = m0 * pose[0] + m1 * pose[1] + m2 * pose[2]  + pose[3];
        float pc1 = m0 * pose[4] + m1 * pose[5] + m2 * pose[6]  + pose[7];
        float z   = m0 * pose[8] + m1 * pose[9] + m2 * pose[10] + pose[11];
        // IEEE rn div/mul/add, NO fma (matches reference; measured best)
        float x = __fadd_rn(__fmul_rn(__fdiv_rn(pc0, z), FXc), CXc);
        float y = __fadd_rn(__fmul_rn(__fdiv_rn(pc1, z), FYc), CYc);
        bool ok = (tbase + q < n) && (x >= 0.0f) && (x < (float)IMG_W) &&
                  (y >= 0.0f) && (y < (float)IMG_H) && (z > 0.0f);
        if (ok) {
            u32 pid = (u32)((int)floorf(y) * IMG_W + (int)floorf(x));
            u64 key = pack_key(z, (u32)(tbase + q));
            u32 pos = atomicAdd(&g_cnt[pid], 1u);
            if (pos < SLOTS) {
                g_slot[(size_t)pos * HW + pid] = key;
            } else {
                u32 o = atomicAdd(&g_cnt[HW], 1u);
                if (o < OVCAP) { g_ovk[o] = key; g_ovp[o] = pid; }
            }
        }
    }
}

// ---------------- fused sort + exact compositing render -------------------
// Sorted order: ascending u64 key == (z desc, idx asc) == reference lexsort.
// Exact compositing: T_i = prod_{j>i}(1 - w_j); contrib_i = w_i * T_i.
#define CSW(a, b) { u64 _lo = (a) < (b) ? (a) : (b); \
                    u64 _hi = (a) < (b) ? (b) : (a); (a) = _lo; (b) = _hi; }

__global__ void __launch_bounds__(256, 8)
render_kernel(const float* __restrict__ opac,
              const float* __restrict__ feats,
              float* __restrict__ out)
{
    int p = blockIdx.x * blockDim.x + threadIdx.x;
    if (p >= HW) return;
    u32 k = g_cnt[p];
    u64 s0 = g_slot[p];              // speculative (valid iff k>=1), coalesced

    float img0 = 0.0f, img1 = 0.0f, img2 = 0.0f;
    float dep = 0.0f;
    float Lsum = 0.0f;

    if (k == 1) {
        u32 idx = (u32)s0;
        float wv = opac[idx];
        img0 = wv * feats[3 * idx + 0];
        img1 = wv * feats[3 * idx + 1];
        img2 = wv * feats[3 * idx + 2];
        dep  = wv * key_z(s0);
        Lsum = log1pf(-wv);
    } else if (k > 1 && k <= 4) {
        u64 a[4];
        a[0] = s0;
#pragma unroll
        for (int i = 1; i < 4; i++)
            a[i] = ((u32)i < k) ? g_slot[(size_t)i * HW + p] : ~0ull;
        CSW(a[0], a[1]); CSW(a[2], a[3]);
        CSW(a[0], a[2]); CSW(a[1], a[3]);
        CSW(a[1], a[2]);
        float w[4];
#pragma unroll
        for (int i = 0; i < 4; i++)
            w[i] = ((u32)i < k) ? opac[(u32)a[i]] : 0.0f;
        float T = 1.0f;
#pragma unroll
        for (int i = 3; i >= 0; i--) {
            if ((u32)i < k) {
                float contrib = w[i] * T;
                u32 idx = (u32)a[i];
                img0 += contrib * feats[3 * idx + 0];
                img1 += contrib * feats[3 * idx + 1];
                img2 += contrib * feats[3 * idx + 2];
                dep  += contrib * key_z(a[i]);
                Lsum += log1pf(-w[i]);
                T *= (1.0f - w[i]);
            }
        }
    } else if (k > 4 && k <= 8) {
        u64 a[8];
        a[0] = s0;
#pragma unroll
        for (int i = 1; i < 8; i++)
            a[i] = ((u32)i < k) ? g_slot[(size_t)i * HW + p] : ~0ull;
        // Batcher odd-even merge sort, 8 inputs, 19 CEs
        CSW(a[0], a[1]); CSW(a[2], a[3]); CSW(a[4], a[5]); CSW(a[6], a[7]);
        CSW(a[0], a[2]); CSW(a[1], a[3]); CSW(a[4], a[6]); CSW(a[5], a[7]);
        CSW(a[1], a[2]); CSW(a[5], a[6]);
        CSW(a[0], a[4]); CSW(a[1], a[5]); CSW(a[2], a[6]); CSW(a[3], a[7]);
        CSW(a[2], a[4]); CSW(a[3], a[5]);
        CSW(a[1], a[2]); CSW(a[3], a[4]); CSW(a[5], a[6]);
        float w[8];
#pragma unroll
        for (int i = 0; i < 8; i++)
            w[i] = ((u32)i < k) ? opac[(u32)a[i]] : 0.0f;
        float T = 1.0f;
#pragma unroll
        for (int i = 7; i >= 0; i--) {
            if ((u32)i < k) {
                float contrib = w[i] * T;
                u32 idx = (u32)a[i];
                img0 += contrib * feats[3 * idx + 0];
                img1 += contrib * feats[3 * idx + 1];
                img2 += contrib * feats[3 * idx + 2];
                dep  += contrib * key_z(a[i]);
                Lsum += log1pf(-w[i]);
                T *= (1.0f - w[i]);
            }
        }
    } else if (k > 8) {
        // overflow pixel (expected ~0-2 per frame): merge slots + overflow
        u64 list[LMAX];
        int mcount = 0;
        list[mcount++] = s0;
        for (int i = 1; i < SLOTS; i++)
            list[mcount++] = g_slot[(size_t)i * HW + p];
        u32 ovn = g_cnt[HW];
        if (ovn > OVCAP) ovn = OVCAP;
        for (u32 j = 0; j < ovn; j++)
            if (g_ovp[j] == (u32)p && mcount < LMAX) list[mcount++] = g_ovk[j];
        // insertion sort ascending
        for (int i = 1; i < mcount; i++) {
            u64 key = list[i];
            int j = i - 1;
            while (j >= 0 && list[j] > key) { list[j + 1] = list[j]; j--; }
            list[j + 1] = key;
        }
        float T = 1.0f;
        for (int i = mcount - 1; i >= 0; i--) {
            u64 key = list[i];
            u32 idx = (u32)key;
            float wv = opac[idx];
            float contrib = wv * T;
            img0 += contrib * feats[3 * idx + 0];
            img1 += contrib * feats[3 * idx + 1];
            img2 += contrib * feats[3 * idx + 2];
            dep  += contrib * key_z(key);
            Lsum += log1pf(-wv);
            T *= (1.0f - wv);
        }
    }

    out[0 * HW + p] = img0;
    out[1 * HW + p] = img1;
    out[2 * HW + p] = img2;
    out[3 * HW + p] = dep;
    out[4 * HW + p] = 1.0f - expf(Lsum);
}

// ---------------- launch: 3 graph nodes ----------------
extern "C" void kernel_launch(void* const* d_in, const int* in_sizes, int n_in,
                              void* d_out, int out_size)
{
    const float* means = (const float*)d_in[0];
    const float* opac  = (const float*)d_in[1];
    const float* feats = (const float*)d_in[2];
    const float* pose  = (const float*)d_in[3];
    float* out = (float*)d_out;

    int n = in_sizes[0] / 3;

    void* cnt_addr = nullptr; cudaGetSymbolAddress(&cnt_addr, g_cnt);
    cudaMemsetAsync(cnt_addr, 0, (HW + 2) * sizeof(u32), 0);

    int npt = (n + PPT - 1) / PPT;
    project_scatter_kernel<<<(npt + PRJ_TPB - 1) / PRJ_TPB, PRJ_TPB>>>(
        (const float4*)means, means, pose, n);
    render_kernel<<<(HW + 255) / 256, 256>>>(opac, feats, out);
}